// round 12
// baseline (speedup 1.0000x reference)
#include <cuda_runtime.h>
#include <cuda_fp16.h>
#include <math.h>
#include <stdint.h>

#define HEADS 12
#define DH 64
#define DIM 768
#define BATCH 8
#define SEQ 1024
#define ROWS (BATCH * SEQ)   // 8192

#define QSCALE 0.1803368801111204f   // 0.125 * log2(e)

// ---------------- scratch ----------------
__device__ __half g_Xh[ROWS * DIM];
__device__ __half g_Yh[ROWS * DIM];
__device__ __half g_WTq[DIM * DIM];
__device__ __half g_WTk[DIM * DIM];
__device__ __half g_WTv[DIM * DIM];
__device__ __half g_WTo[DIM * DIM];
__device__ __half g_Qh[ROWS * DIM];
__device__ __half g_Kh[ROWS * DIM];
__device__ __half g_Vh[ROWS * DIM];
__device__ __half g_Aoh[ROWS * DIM];
__device__ float g_cosT[512];
__device__ float g_sinT[512];

// ---------------- helpers ----------------
__device__ __forceinline__ uint32_t smem_u32(const void* p) {
    uint32_t a;
    asm("{ .reg .u64 t; cvta.to.shared.u64 t, %1; cvt.u32.u64 %0, t; }" : "=r"(a) : "l"(p));
    return a;
}
__device__ __forceinline__ float ex2f(float x) {
    float y;
    asm("ex2.approx.ftz.f32 %0, %1;" : "=f"(y) : "f"(x));
    return y;
}

#define LDSM_X4(r0, r1, r2, r3, addr)                                          \
    asm volatile("ldmatrix.sync.aligned.m8n8.x4.shared.b16 {%0,%1,%2,%3}, [%4];" \
                 : "=r"(r0), "=r"(r1), "=r"(r2), "=r"(r3) : "r"(addr))

#define LDSM_X4_T(r0, r1, r2, r3, addr)                                        \
    asm volatile("ldmatrix.sync.aligned.m8n8.x4.trans.shared.b16 {%0,%1,%2,%3}, [%4];" \
                 : "=r"(r0), "=r"(r1), "=r"(r2), "=r"(r3) : "r"(addr))

#define MMA16816(c, a, b0, b1)                                                 \
    asm volatile("mma.sync.aligned.m16n8k16.row.col.f32.f16.f16.f32 "          \
                 "{%0,%1,%2,%3}, {%4,%5,%6,%7}, {%8,%9}, {%0,%1,%2,%3};"       \
                 : "+f"((c)[0]), "+f"((c)[1]), "+f"((c)[2]), "+f"((c)[3])      \
                 : "r"((a)[0]), "r"((a)[1]), "r"((a)[2]), "r"((a)[3]),         \
                   "r"(b0), "r"(b1))

#define CP_ASYNC16(dst, src)                                                   \
    asm volatile("cp.async.cg.shared.global [%0], [%1], 16;" :: "r"(dst), "l"(src))
#define CP_COMMIT() asm volatile("cp.async.commit_group;" ::: "memory")
#define CP_WAIT(n)  asm volatile("cp.async.wait_group %0;" :: "n"(n) : "memory")

// ---------------- float -> half (x and y in one launch) ----------------
__global__ void f2h2_kernel(const float* __restrict__ x, const float* __restrict__ y,
                            __half* __restrict__ Xh, __half* __restrict__ Yh, int n4) {
    int i = blockIdx.x * blockDim.x + threadIdx.x;
    if (i >= n4) return;
    const float* src = blockIdx.y ? y : x;
    __half* dst = blockIdx.y ? Yh : Xh;
    float4 v = ((const float4*)src)[i];
    __half2 lo = __floats2half2_rn(v.x, v.y);
    __half2 hi = __floats2half2_rn(v.z, v.w);
    uint2 o;
    o.x = *(uint32_t*)&lo;
    o.y = *(uint32_t*)&hi;
    ((uint2*)dst)[i] = o;
}

// ---------------- 4 weight transposes + RoPE table init in one launch ----------------
__global__ void transpose4_kernel(const float* __restrict__ Wq, const float* __restrict__ Wk,
                                  const float* __restrict__ Wv, const float* __restrict__ Wo,
                                  __half* __restrict__ Tq, __half* __restrict__ Tk,
                                  __half* __restrict__ Tv, __half* __restrict__ To) {
    const int z = blockIdx.z;
    if (z == 0 && blockIdx.x == 0 && blockIdx.y == 0) {
        int t = threadIdx.y * 32 + threadIdx.x;
        #pragma unroll
        for (int rep = 0; rep < 2; ++rep) {
            int i = t + rep * 256;
            int p = i >> 4;
            int f = i & 15;
            double inv = pow(100.0, -((double)(2 * f)) / 32.0);
            double fr = (double)p * inv;
            g_cosT[i] = (float)cos(fr);
            g_sinT[i] = (float)sin(fr);
        }
    }
    const float* W = (z == 0) ? Wq : (z == 1) ? Wk : (z == 2) ? Wv : Wo;
    __half* T = (z == 0) ? Tq : (z == 1) ? Tk : (z == 2) ? Tv : To;
    __shared__ float tile[32][33];
    int bx = blockIdx.x * 32;
    int by = blockIdx.y * 32;
    int x = threadIdx.x, y = threadIdx.y;
    #pragma unroll
    for (int j = 0; j < 4; ++j)
        tile[y + 8 * j][x] = W[(by + y + 8 * j) * DIM + bx + x];
    __syncthreads();
    #pragma unroll
    for (int j = 0; j < 4; ++j)
        T[(size_t)(bx + y + 8 * j) * DIM + by + x] = __float2half(tile[x][y + 8 * j]);
}

// ---------------- GEMM tile constants ----------------
#define NKT (DIM / 64)
#define AS_BYTES (128 * 128)
#define STAGE_B (2 * AS_BYTES)
#define GEMM_SMEM (2 * STAGE_B)

// ---------------- fused Q/K/V projection GEMM (one launch, z picks mode) ----------------
__global__ __launch_bounds__(256, 2) void qkv_gemm_kernel(
    const __half* __restrict__ Xh, const __half* __restrict__ Yh,
    const __half* __restrict__ WTq, const __half* __restrict__ WTk, const __half* __restrict__ WTv,
    const float* __restrict__ bq, const float* __restrict__ bk, const float* __restrict__ bv,
    const int* __restrict__ pos_q, const int* __restrict__ pos_kv,
    __half* __restrict__ Qh, __half* __restrict__ Kh, __half* __restrict__ Vh)
{
    extern __shared__ char sm[];
    const uint32_t sbase = smem_u32(sm);
    const int z = blockIdx.z;
    const __half* A = (z == 0) ? Xh : Yh;
    const __half* B = (z == 0) ? WTq : (z == 1) ? WTk : WTv;
    const float* bias = (z == 0) ? bq : (z == 1) ? bk : bv;
    const int* pos = (z == 0) ? pos_q : pos_kv;
    __half* Ch = (z == 0) ? Qh : (z == 1) ? Kh : Vh;

    const int tid  = threadIdx.x;
    const int lane = tid & 31;
    const int wid  = tid >> 5;
    const int warpM = wid & 3;
    const int warpN = wid >> 2;
    const int m0 = blockIdx.y * 128;
    const int n0 = blockIdx.x * 128;

    float c[2][8][4];
    #pragma unroll
    for (int i = 0; i < 2; ++i)
        #pragma unroll
        for (int j = 0; j < 8; ++j)
            #pragma unroll
            for (int q = 0; q < 4; ++q) c[i][j][q] = 0.f;

    const int rr0 = tid >> 3;
    const int cc  = tid & 7;

    auto issue_stage = [&](int kt, int s) {
        #pragma unroll
        for (int i = 0; i < 4; ++i) {
            int r = rr0 + i * 32;
            uint32_t sw = (uint32_t)(r * 128 + ((cc ^ (r & 7)) << 4));
            uint32_t da = sbase + s * STAGE_B + sw;
            uint32_t db = da + AS_BYTES;
            const char* ga = (const char*)(A + (size_t)(m0 + r) * DIM + kt * 64 + cc * 8);
            const char* gb = (const char*)(B + (size_t)(n0 + r) * DIM + kt * 64 + cc * 8);
            CP_ASYNC16(da, ga);
            CP_ASYNC16(db, gb);
        }
        CP_COMMIT();
    };

    const int lrow8 = ((lane >> 3) & 1) * 8 + (lane & 7);
    const int lcol16 = (lane >> 4) * 16;

    issue_stage(0, 0);

    for (int kt = 0; kt < NKT; ++kt) {
        CP_WAIT(0);
        __syncthreads();
        if (kt + 1 < NKT) issue_stage(kt + 1, (kt + 1) & 1);

        const uint32_t ab = sbase + (kt & 1) * STAGE_B;
        const uint32_t bb = ab + AS_BYTES;

        #pragma unroll
        for (int ks = 0; ks < 4; ++ks) {
            const int kb = ks * 32;
            uint32_t af[2][4];
            #pragma unroll
            for (int i = 0; i < 2; ++i) {
                int row = warpM * 32 + i * 16 + lrow8;
                int col = kb + lcol16;
                uint32_t ad = ab + row * 128 + ((((col >> 4) ^ (row & 7)) & 7) << 4);
                LDSM_X4(af[i][0], af[i][1], af[i][2], af[i][3], ad);
            }
            uint32_t bf[4][4];
            #pragma unroll
            for (int jj = 0; jj < 4; ++jj) {
                int nrow = warpN * 64 + jj * 16 + lrow8;
                int col = kb + lcol16;
                uint32_t bd = bb + nrow * 128 + ((((col >> 4) ^ (nrow & 7)) & 7) << 4);
                LDSM_X4(bf[jj][0], bf[jj][1], bf[jj][2], bf[jj][3], bd);
            }
            #pragma unroll
            for (int i = 0; i < 2; ++i) {
                #pragma unroll
                for (int j = 0; j < 8; ++j) {
                    const int jj = j >> 1, sel = j & 1;
                    MMA16816(c[i][j], af[i], bf[jj][sel], bf[jj][sel + 2]);
                }
            }
        }
    }

    // ---------------- fused epilogue ----------------
    if (z == 2) {
        #pragma unroll
        for (int i = 0; i < 2; ++i) {
            #pragma unroll
            for (int j = 0; j < 8; ++j) {
                int row = m0 + warpM * 32 + i * 16 + (lane >> 2);
                int col = n0 + warpN * 64 + j * 8 + (lane & 3) * 2;
                float b0v = bias[col], b1v = bias[col + 1];
                *(__half2*)&Ch[(size_t)row * DIM + col] =
                    __floats2half2_rn(c[i][j][0] + b0v, c[i][j][1] + b1v);
                *(__half2*)&Ch[(size_t)(row + 8) * DIM + col] =
                    __floats2half2_rn(c[i][j][2] + b0v, c[i][j][3] + b1v);
            }
        }
    } else {
        const float scale = (z == 0) ? QSCALE : 1.0f;
        #pragma unroll
        for (int i = 0; i < 2; ++i) {
            int rowA = m0 + warpM * 32 + i * 16 + (lane >> 2);
            int rowB = rowA + 8;
            int pA0 = pos[2 * rowA], pA1 = pos[2 * rowA + 1];
            int pB0 = pos[2 * rowB], pB1 = pos[2 * rowB + 1];
            #pragma unroll
            for (int jj = 0; jj < 4; ++jj) {
                const int j = (jj < 2) ? jj : jj + 2;   // 0,1,4,5
                const int half = (j >= 4);
                int col = n0 + warpN * 64 + j * 8 + (lane & 3) * 2;
                int f0 = (j & 1) * 8 + (lane & 3) * 2;
                int pA = half ? pA1 : pA0;
                int pB = half ? pB1 : pB0;
                float cA0 = g_cosT[pA * 16 + f0], cA1 = g_cosT[pA * 16 + f0 + 1];
                float sA0 = g_sinT[pA * 16 + f0], sA1 = g_sinT[pA * 16 + f0 + 1];
                float cB0 = g_cosT[pB * 16 + f0], cB1 = g_cosT[pB * 16 + f0 + 1];
                float sB0 = g_sinT[pB * 16 + f0], sB1 = g_sinT[pB * 16 + f0 + 1];
                float b1x = bias[col], b1y = bias[col + 1];
                float b2x = bias[col + 16], b2y = bias[col + 17];

                {
                    float v1x = c[i][j][0] + b1x,     v1y = c[i][j][1] + b1y;
                    float v2x = c[i][j + 2][0] + b2x, v2y = c[i][j + 2][1] + b2y;
                    *(__half2*)&Ch[(size_t)rowA * DIM + col] =
                        __floats2half2_rn((v1x * cA0 - v2x * sA0) * scale,
                                          (v1y * cA1 - v2y * sA1) * scale);
                    *(__half2*)&Ch[(size_t)rowA * DIM + col + 16] =
                        __floats2half2_rn((v2x * cA0 + v1x * sA0) * scale,
                                          (v2y * cA1 + v1y * sA1) * scale);
                }
                {
                    float v1x = c[i][j][2] + b1x,     v1y = c[i][j][3] + b1y;
                    float v2x = c[i][j + 2][2] + b2x, v2y = c[i][j + 2][3] + b2y;
                    *(__half2*)&Ch[(size_t)rowB * DIM + col] =
                        __floats2half2_rn((v1x * cB0 - v2x * sB0) * scale,
                                          (v1y * cB1 - v2y * sB1) * scale);
                    *(__half2*)&Ch[(size_t)rowB * DIM + col + 16] =
                        __floats2half2_rn((v2x * cB0 + v1x * sB0) * scale,
                                          (v2y * cB1 + v1y * sB1) * scale);
                }
            }
        }
    }
}

// ---------------- final output GEMM: out = Aoh @ WTo^T + bo (fp32) ----------------
__global__ __launch_bounds__(256, 2) void out_gemm_kernel(
    const __half* __restrict__ A, const __half* __restrict__ B,
    const float* __restrict__ bias, float* __restrict__ Cf)
{
    extern __shared__ char sm[];
    const uint32_t sbase = smem_u32(sm);
    const int tid  = threadIdx.x;
    const int lane = tid & 31;
    const int wid  = tid >> 5;
    const int warpM = wid & 3;
    const int warpN = wid >> 2;
    const int m0 = blockIdx.y * 128;
    const int n0 = blockIdx.x * 128;

    float c[2][8][4];
    #pragma unroll
    for (int i = 0; i < 2; ++i)
        #pragma unroll
        for (int j = 0; j < 8; ++j)
            #pragma unroll
            for (int q = 0; q < 4; ++q) c[i][j][q] = 0.f;

    const int rr0 = tid >> 3;
    const int cc  = tid & 7;

    auto issue_stage = [&](int kt, int s) {
        #pragma unroll
        for (int i = 0; i < 4; ++i) {
            int r = rr0 + i * 32;
            uint32_t sw = (uint32_t)(r * 128 + ((cc ^ (r & 7)) << 4));
            uint32_t da = sbase + s * STAGE_B + sw;
            uint32_t db = da + AS_BYTES;
            const char* ga = (const char*)(A + (size_t)(m0 + r) * DIM + kt * 64 + cc * 8);
            const char* gb = (const char*)(B + (size_t)(n0 + r) * DIM + kt * 64 + cc * 8);
            CP_ASYNC16(da, ga);
            CP_ASYNC16(db, gb);
        }
        CP_COMMIT();
    };

    const int lrow8 = ((lane >> 3) & 1) * 8 + (lane & 7);
    const int lcol16 = (lane >> 4) * 16;

    issue_stage(0, 0);

    for (int kt = 0; kt < NKT; ++kt) {
        CP_WAIT(0);
        __syncthreads();
        if (kt + 1 < NKT) issue_stage(kt + 1, (kt + 1) & 1);

        const uint32_t ab = sbase + (kt & 1) * STAGE_B;
        const uint32_t bb = ab + AS_BYTES;

        #pragma unroll
        for (int ks = 0; ks < 4; ++ks) {
            const int kb = ks * 32;
            uint32_t af[2][4];
            #pragma unroll
            for (int i = 0; i < 2; ++i) {
                int row = warpM * 32 + i * 16 + lrow8;
                int col = kb + lcol16;
                uint32_t ad = ab + row * 128 + ((((col >> 4) ^ (row & 7)) & 7) << 4);
                LDSM_X4(af[i][0], af[i][1], af[i][2], af[i][3], ad);
            }
            uint32_t bf[4][4];
            #pragma unroll
            for (int jj = 0; jj < 4; ++jj) {
                int nrow = warpN * 64 + jj * 16 + lrow8;
                int col = kb + lcol16;
                uint32_t bd = bb + nrow * 128 + ((((col >> 4) ^ (nrow & 7)) & 7) << 4);
                LDSM_X4(bf[jj][0], bf[jj][1], bf[jj][2], bf[jj][3], bd);
            }
            #pragma unroll
            for (int i = 0; i < 2; ++i) {
                #pragma unroll
                for (int j = 0; j < 8; ++j) {
                    const int jj = j >> 1, sel = j & 1;
                    MMA16816(c[i][j], af[i], bf[jj][sel], bf[jj][sel + 2]);
                }
            }
        }
    }

    #pragma unroll
    for (int i = 0; i < 2; ++i) {
        #pragma unroll
        for (int j = 0; j < 8; ++j) {
            int row = m0 + warpM * 32 + i * 16 + (lane >> 2);
            int col = n0 + warpN * 64 + j * 8 + (lane & 3) * 2;
            float b0v = bias[col], b1v = bias[col + 1];
            float2 o0 = {c[i][j][0] + b0v, c[i][j][1] + b1v};
            float2 o1 = {c[i][j][2] + b0v, c[i][j][3] + b1v};
            *(float2*)&Cf[(size_t)row * DIM + col] = o0;
            *(float2*)&Cf[(size_t)(row + 8) * DIM + col] = o1;
        }
    }
}

// ---------------- fp16 tensor-core flash attention: 128q x 128kv per iteration ----------------
// stage: K (16K) + V (16K) = 32 KB double-buffered; Q tile 16 KB.
#define FS_STAGE 32768
#define FS_Q_OFF (2 * FS_STAGE)                 // 65536
#define FS_SMEM (FS_Q_OFF + 16384)              // 81920

__global__ __launch_bounds__(256) void flash16_kernel(
    const __half* __restrict__ Qh, const __half* __restrict__ Kh,
    const __half* __restrict__ Vh, __half* __restrict__ Ao)
{
    extern __shared__ char sm[];
    const uint32_t sb = smem_u32(sm);
    const int tid  = threadIdx.x;
    const int lane = tid & 31;
    const int wid  = tid >> 5;
    const int qb   = blockIdx.x * 128;
    const int h    = blockIdx.y;
    const int b    = blockIdx.z;
    const size_t qrow0 = (size_t)b * SEQ + qb;
    const int colh = h * DH;

    const int lrow8  = ((lane >> 3) & 1) * 8 + (lane & 7);
    const int lcol16 = (lane >> 4) * 16;

    // Q tile load (128 x 64)
    #pragma unroll
    for (int i = 0; i < 4; ++i) {
        int idx = tid + i * 256;
        int r = idx >> 3, c = idx & 7;
        uint32_t sw = (uint32_t)(r * 128 + ((c ^ (r & 7)) << 4));
        size_t goff = (qrow0 + r) * DIM + colh + c * 8;
        CP_ASYNC16(sb + FS_Q_OFF + sw, (const char*)(Qh + goff));
    }
    CP_COMMIT();

    // KV stage: 128 rows of K then 128 rows of V
    auto issue_kv = [&](int kt, int s) {
        const size_t rowbase = (size_t)b * SEQ + (size_t)kt * 128;
        const uint32_t st = sb + s * FS_STAGE;
        #pragma unroll
        for (int i = 0; i < 4; ++i) {
            int idx = tid + i * 256;
            int r = idx >> 3, c = idx & 7;   // r: 0..127
            uint32_t sw = (uint32_t)(r * 128 + ((c ^ (r & 7)) << 4));
            size_t goff = (rowbase + r) * DIM + colh + c * 8;
            CP_ASYNC16(st + sw,         (const char*)(Kh + goff));
            CP_ASYNC16(st + 16384 + sw, (const char*)(Vh + goff));
        }
        CP_COMMIT();
    };

    issue_kv(0, 0);
    CP_WAIT(0);
    __syncthreads();

    uint32_t qhf[4][4];
    #pragma unroll
    for (int kc = 0; kc < 4; ++kc) {
        int row = wid * 16 + lrow8;
        int col = kc * 32 + lcol16;
        uint32_t ad = sb + FS_Q_OFF + row * 128 + ((((col >> 4) ^ (row & 7)) & 7) << 4);
        LDSM_X4(qhf[kc][0], qhf[kc][1], qhf[kc][2], qhf[kc][3], ad);
    }

    float o[8][4];
    #pragma unroll
    for (int i = 0; i < 8; ++i)
        #pragma unroll
        for (int q = 0; q < 4; ++q) o[i][q] = 0.f;
    float m0 = -1e30f, m1 = -1e30f, l0 = 0.f, l1 = 0.f;   // l: per-thread partials

    for (int kt = 0; kt < SEQ / 128; ++kt) {     // 8 iterations of 128 kv
        if (kt) {
            CP_WAIT(0);
            __syncthreads();
        }
        if (kt + 1 < SEQ / 128) issue_kv(kt + 1, (kt + 1) & 1);

        const uint32_t kb = sb + (kt & 1) * FS_STAGE;
        const uint32_t vb = kb + 16384;

        float s[16][4];
        #pragma unroll
        for (int i = 0; i < 16; ++i)
            #pragma unroll
            for (int q = 0; q < 4; ++q) s[i][q] = 0.f;

        // S = Q K^T over 128 kv (8 n-blocks of 16)
        #pragma unroll
        for (int kc = 0; kc < 4; ++kc) {
            const int col = kc * 32 + lcol16;
            #pragma unroll
            for (int nb2 = 0; nb2 < 8; ++nb2) {
                int row = nb2 * 16 + lrow8;
                uint32_t ad = kb + row * 128 + ((((col >> 4) ^ (row & 7)) & 7) << 4);
                uint32_t f0, f1, f2, f3;
                LDSM_X4(f0, f1, f2, f3, ad);
                MMA16816(s[2 * nb2],     qhf[kc], f0, f2);
                MMA16816(s[2 * nb2 + 1], qhf[kc], f1, f3);
            }
        }

        // single softmax phase over 128 columns
        float mx0 = -1e30f, mx1 = -1e30f;
        #pragma unroll
        for (int nb = 0; nb < 16; ++nb) {
            mx0 = fmaxf(mx0, fmaxf(s[nb][0], s[nb][1]));
            mx1 = fmaxf(mx1, fmaxf(s[nb][2], s[nb][3]));
        }
        mx0 = fmaxf(mx0, __shfl_xor_sync(0xffffffffu, mx0, 1));
        mx0 = fmaxf(mx0, __shfl_xor_sync(0xffffffffu, mx0, 2));
        mx1 = fmaxf(mx1, __shfl_xor_sync(0xffffffffu, mx1, 1));
        mx1 = fmaxf(mx1, __shfl_xor_sync(0xffffffffu, mx1, 2));
        float mn0 = fmaxf(m0, mx0), mn1 = fmaxf(m1, mx1);
        float cr0 = ex2f(m0 - mn0), cr1 = ex2f(m1 - mn1);
        m0 = mn0; m1 = mn1;

        uint32_t a[8][4];
        float ls0 = 0.f, ls1 = 0.f;
        #pragma unroll
        for (int nb = 0; nb < 16; ++nb) {
            float p0 = ex2f(s[nb][0] - mn0);
            float p1 = ex2f(s[nb][1] - mn0);
            float p2 = ex2f(s[nb][2] - mn1);
            float p3 = ex2f(s[nb][3] - mn1);
            ls0 += p0 + p1;
            ls1 += p2 + p3;
            __half2 h01 = __floats2half2_rn(p0, p1);
            __half2 h23 = __floats2half2_rn(p2, p3);
            int kc = nb >> 1;
            if ((nb & 1) == 0) {
                a[kc][0] = *(uint32_t*)&h01;
                a[kc][1] = *(uint32_t*)&h23;
            } else {
                a[kc][2] = *(uint32_t*)&h01;
                a[kc][3] = *(uint32_t*)&h23;
            }
        }
        // per-thread l partials (corr is uniform across the lane quad -> exact)
        l0 = l0 * cr0 + ls0;
        l1 = l1 * cr1 + ls1;
        #pragma unroll
        for (int db = 0; db < 8; ++db) {
            o[db][0] *= cr0; o[db][1] *= cr0;
            o[db][2] *= cr1; o[db][3] *= cr1;
        }

        // O += P V over 128 kv (8 k-groups of 16)
        #pragma unroll
        for (int kc = 0; kc < 8; ++kc) {
            int row = kc * 16 + lrow8;
            #pragma unroll
            for (int db2 = 0; db2 < 4; ++db2) {
                int col = db2 * 32 + lcol16;
                uint32_t ad = vb + row * 128 + ((((col >> 4) ^ (row & 7)) & 7) << 4);
                uint32_t f0, f1, f2, f3;
                LDSM_X4_T(f0, f1, f2, f3, ad);
                MMA16816(o[2 * db2],     a[kc], f0, f1);
                MMA16816(o[2 * db2 + 1], a[kc], f2, f3);
            }
        }
    }

    // final cross-lane l reduction (deferred)
    l0 += __shfl_xor_sync(0xffffffffu, l0, 1);
    l0 += __shfl_xor_sync(0xffffffffu, l0, 2);
    l1 += __shfl_xor_sync(0xffffffffu, l1, 1);
    l1 += __shfl_xor_sync(0xffffffffu, l1, 2);

    float inv0 = 1.0f / l0, inv1 = 1.0f / l1;
    size_t r0 = qrow0 + wid * 16 + (lane >> 2);
    size_t r1 = r0 + 8;
    int cb = colh + (lane & 3) * 2;
    #pragma unroll
    for (int db = 0; db < 8; ++db) {
        __half2 w0 = __floats2half2_rn(o[db][0] * inv0, o[db][1] * inv0);
        __half2 w1 = __floats2half2_rn(o[db][2] * inv1, o[db][3] * inv1);
        *(__half2*)&Ao[r0 * DIM + cb + db * 8] = w0;
        *(__half2*)&Ao[r1 * DIM + cb + db * 8] = w1;
    }
}

// ---------------- launch ----------------
extern "C" void kernel_launch(void* const* d_in, const int* in_sizes, int n_in,
                              void* d_out, int out_size) {
    const float* x      = (const float*)d_in[0];
    const float* y      = (const float*)d_in[1];
    const int*   pos_q  = (const int*)d_in[2];
    const int*   pos_kv = (const int*)d_in[3];
    const float* Wq = (const float*)d_in[4];
    const float* bq = (const float*)d_in[5];
    const float* Wk = (const float*)d_in[6];
    const float* bk = (const float*)d_in[7];
    const float* Wv = (const float*)d_in[8];
    const float* bv = (const float*)d_in[9];
    const float* Wo = (const float*)d_in[10];
    const float* bo = (const float*)d_in[11];
    float* out = (float*)d_out;

    __half *Xh, *Yh, *WTq, *WTk, *WTv, *WTo;
    __half *Qhp, *Khp, *Vhp, *Aohp;
    cudaGetSymbolAddress((void**)&Xh, g_Xh);
    cudaGetSymbolAddress((void**)&Yh, g_Yh);
    cudaGetSymbolAddress((void**)&WTq, g_WTq);
    cudaGetSymbolAddress((void**)&WTk, g_WTk);
    cudaGetSymbolAddress((void**)&WTv, g_WTv);
    cudaGetSymbolAddress((void**)&WTo, g_WTo);
    cudaGetSymbolAddress((void**)&Qhp, g_Qh);
    cudaGetSymbolAddress((void**)&Khp, g_Kh);
    cudaGetSymbolAddress((void**)&Vhp, g_Vh);
    cudaGetSymbolAddress((void**)&Aohp, g_Aoh);

    cudaFuncSetAttribute(qkv_gemm_kernel, cudaFuncAttributeMaxDynamicSharedMemorySize, GEMM_SMEM);
    cudaFuncSetAttribute(out_gemm_kernel, cudaFuncAttributeMaxDynamicSharedMemorySize, GEMM_SMEM);
    cudaFuncSetAttribute(flash16_kernel, cudaFuncAttributeMaxDynamicSharedMemorySize, FS_SMEM);

    const int n4 = (ROWS * DIM) / 4;
    f2h2_kernel<<<dim3((n4 + 255) / 256, 2), 256>>>(x, y, Xh, Yh, n4);

    transpose4_kernel<<<dim3(DIM / 32, DIM / 32, 4), dim3(32, 8)>>>(
        Wq, Wk, Wv, Wo, WTq, WTk, WTv, WTo);

    qkv_gemm_kernel<<<dim3(DIM / 128, ROWS / 128, 3), 256, GEMM_SMEM>>>(
        Xh, Yh, WTq, WTk, WTv, bq, bk, bv, pos_q, pos_kv,
        Qhp, Khp, Vhp);

    flash16_kernel<<<dim3(SEQ / 128, HEADS, BATCH), 256, FS_SMEM>>>(
        Qhp, Khp, Vhp, Aohp);

    out_gemm_kernel<<<dim3(DIM / 128, ROWS / 128), 256, GEMM_SMEM>>>(Aohp, WTo, bo, out);
}

// round 13
// speedup vs baseline: 1.0237x; 1.0237x over previous
#include <cuda_runtime.h>
#include <cuda_fp16.h>
#include <math.h>
#include <stdint.h>

#define HEADS 12
#define DH 64
#define DIM 768
#define BATCH 8
#define SEQ 1024
#define ROWS (BATCH * SEQ)   // 8192

#define QSCALE 0.1803368801111204f   // 0.125 * log2(e)

// ---------------- scratch ----------------
__device__ __half g_Xh[ROWS * DIM];
__device__ __half g_Yh[ROWS * DIM];
__device__ __half g_WTq[DIM * DIM];
__device__ __half g_WTk[DIM * DIM];
__device__ __half g_WTv[DIM * DIM];
__device__ __half g_WTo[DIM * DIM];
__device__ __half g_Qh[ROWS * DIM];
__device__ __half g_Kh[ROWS * DIM];
__device__ __half g_Vh[ROWS * DIM];
__device__ __half g_Aoh[ROWS * DIM];
__device__ float g_cosT[512];
__device__ float g_sinT[512];

// ---------------- helpers ----------------
__device__ __forceinline__ uint32_t smem_u32(const void* p) {
    uint32_t a;
    asm("{ .reg .u64 t; cvta.to.shared.u64 t, %1; cvt.u32.u64 %0, t; }" : "=r"(a) : "l"(p));
    return a;
}
__device__ __forceinline__ float ex2f(float x) {
    float y;
    asm("ex2.approx.ftz.f32 %0, %1;" : "=f"(y) : "f"(x));
    return y;
}

#define LDSM_X4(r0, r1, r2, r3, addr)                                          \
    asm volatile("ldmatrix.sync.aligned.m8n8.x4.shared.b16 {%0,%1,%2,%3}, [%4];" \
                 : "=r"(r0), "=r"(r1), "=r"(r2), "=r"(r3) : "r"(addr))

#define LDSM_X4_T(r0, r1, r2, r3, addr)                                        \
    asm volatile("ldmatrix.sync.aligned.m8n8.x4.trans.shared.b16 {%0,%1,%2,%3}, [%4];" \
                 : "=r"(r0), "=r"(r1), "=r"(r2), "=r"(r3) : "r"(addr))

#define MMA16816(c, a, b0, b1)                                                 \
    asm volatile("mma.sync.aligned.m16n8k16.row.col.f32.f16.f16.f32 "          \
                 "{%0,%1,%2,%3}, {%4,%5,%6,%7}, {%8,%9}, {%0,%1,%2,%3};"       \
                 : "+f"((c)[0]), "+f"((c)[1]), "+f"((c)[2]), "+f"((c)[3])      \
                 : "r"((a)[0]), "r"((a)[1]), "r"((a)[2]), "r"((a)[3]),         \
                   "r"(b0), "r"(b1))

#define CP_ASYNC16(dst, src)                                                   \
    asm volatile("cp.async.cg.shared.global [%0], [%1], 16;" :: "r"(dst), "l"(src))
#define CP_COMMIT() asm volatile("cp.async.commit_group;" ::: "memory")
#define CP_WAIT(n)  asm volatile("cp.async.wait_group %0;" :: "n"(n) : "memory")

// ---------------- float -> half (x and y in one launch) ----------------
__global__ void f2h2_kernel(const float* __restrict__ x, const float* __restrict__ y,
                            __half* __restrict__ Xh, __half* __restrict__ Yh, int n4) {
    int i = blockIdx.x * blockDim.x + threadIdx.x;
    if (i >= n4) return;
    const float* src = blockIdx.y ? y : x;
    __half* dst = blockIdx.y ? Yh : Xh;
    float4 v = ((const float4*)src)[i];
    __half2 lo = __floats2half2_rn(v.x, v.y);
    __half2 hi = __floats2half2_rn(v.z, v.w);
    uint2 o;
    o.x = *(uint32_t*)&lo;
    o.y = *(uint32_t*)&hi;
    ((uint2*)dst)[i] = o;
}

// ---------------- 4 weight transposes + RoPE table init in one launch ----------------
__global__ void transpose4_kernel(const float* __restrict__ Wq, const float* __restrict__ Wk,
                                  const float* __restrict__ Wv, const float* __restrict__ Wo,
                                  __half* __restrict__ Tq, __half* __restrict__ Tk,
                                  __half* __restrict__ Tv, __half* __restrict__ To) {
    const int z = blockIdx.z;
    if (z == 0 && blockIdx.x == 0 && blockIdx.y == 0) {
        int t = threadIdx.y * 32 + threadIdx.x;
        #pragma unroll
        for (int rep = 0; rep < 2; ++rep) {
            int i = t + rep * 256;
            int p = i >> 4;
            int f = i & 15;
            double inv = pow(100.0, -((double)(2 * f)) / 32.0);
            double fr = (double)p * inv;
            g_cosT[i] = (float)cos(fr);
            g_sinT[i] = (float)sin(fr);
        }
    }
    const float* W = (z == 0) ? Wq : (z == 1) ? Wk : (z == 2) ? Wv : Wo;
    __half* T = (z == 0) ? Tq : (z == 1) ? Tk : (z == 2) ? Tv : To;
    __shared__ float tile[32][33];
    int bx = blockIdx.x * 32;
    int by = blockIdx.y * 32;
    int x = threadIdx.x, y = threadIdx.y;
    #pragma unroll
    for (int j = 0; j < 4; ++j)
        tile[y + 8 * j][x] = W[(by + y + 8 * j) * DIM + bx + x];
    __syncthreads();
    #pragma unroll
    for (int j = 0; j < 4; ++j)
        T[(size_t)(bx + y + 8 * j) * DIM + by + x] = __float2half(tile[x][y + 8 * j]);
}

// ---------------- GEMM tile constants ----------------
#define NKT (DIM / 64)
#define AS_BYTES (128 * 128)
#define STAGE_B (2 * AS_BYTES)
#define GEMM_SMEM (2 * STAGE_B)

// ---------------- fused Q/K/V projection GEMM (one launch, z picks mode) ----------------
__global__ __launch_bounds__(256, 2) void qkv_gemm_kernel(
    const __half* __restrict__ Xh, const __half* __restrict__ Yh,
    const __half* __restrict__ WTq, const __half* __restrict__ WTk, const __half* __restrict__ WTv,
    const float* __restrict__ bq, const float* __restrict__ bk, const float* __restrict__ bv,
    const int* __restrict__ pos_q, const int* __restrict__ pos_kv,
    __half* __restrict__ Qh, __half* __restrict__ Kh, __half* __restrict__ Vh)
{
    extern __shared__ char sm[];
    const uint32_t sbase = smem_u32(sm);
    const int z = blockIdx.z;
    const __half* A = (z == 0) ? Xh : Yh;
    const __half* B = (z == 0) ? WTq : (z == 1) ? WTk : WTv;
    const float* bias = (z == 0) ? bq : (z == 1) ? bk : bv;
    const int* pos = (z == 0) ? pos_q : pos_kv;
    __half* Ch = (z == 0) ? Qh : (z == 1) ? Kh : Vh;

    const int tid  = threadIdx.x;
    const int lane = tid & 31;
    const int wid  = tid >> 5;
    const int warpM = wid & 3;
    const int warpN = wid >> 2;
    const int m0 = blockIdx.y * 128;
    const int n0 = blockIdx.x * 128;

    float c[2][8][4];
    #pragma unroll
    for (int i = 0; i < 2; ++i)
        #pragma unroll
        for (int j = 0; j < 8; ++j)
            #pragma unroll
            for (int q = 0; q < 4; ++q) c[i][j][q] = 0.f;

    const int rr0 = tid >> 3;
    const int cc  = tid & 7;

    auto issue_stage = [&](int kt, int s) {
        #pragma unroll
        for (int i = 0; i < 4; ++i) {
            int r = rr0 + i * 32;
            uint32_t sw = (uint32_t)(r * 128 + ((cc ^ (r & 7)) << 4));
            uint32_t da = sbase + s * STAGE_B + sw;
            uint32_t db = da + AS_BYTES;
            const char* ga = (const char*)(A + (size_t)(m0 + r) * DIM + kt * 64 + cc * 8);
            const char* gb = (const char*)(B + (size_t)(n0 + r) * DIM + kt * 64 + cc * 8);
            CP_ASYNC16(da, ga);
            CP_ASYNC16(db, gb);
        }
        CP_COMMIT();
    };

    const int lrow8 = ((lane >> 3) & 1) * 8 + (lane & 7);
    const int lcol16 = (lane >> 4) * 16;

    issue_stage(0, 0);

    for (int kt = 0; kt < NKT; ++kt) {
        CP_WAIT(0);
        __syncthreads();
        if (kt + 1 < NKT) issue_stage(kt + 1, (kt + 1) & 1);

        const uint32_t ab = sbase + (kt & 1) * STAGE_B;
        const uint32_t bb = ab + AS_BYTES;

        #pragma unroll
        for (int ks = 0; ks < 4; ++ks) {
            const int kb = ks * 32;
            uint32_t af[2][4];
            #pragma unroll
            for (int i = 0; i < 2; ++i) {
                int row = warpM * 32 + i * 16 + lrow8;
                int col = kb + lcol16;
                uint32_t ad = ab + row * 128 + ((((col >> 4) ^ (row & 7)) & 7) << 4);
                LDSM_X4(af[i][0], af[i][1], af[i][2], af[i][3], ad);
            }
            uint32_t bf[4][4];
            #pragma unroll
            for (int jj = 0; jj < 4; ++jj) {
                int nrow = warpN * 64 + jj * 16 + lrow8;
                int col = kb + lcol16;
                uint32_t bd = bb + nrow * 128 + ((((col >> 4) ^ (nrow & 7)) & 7) << 4);
                LDSM_X4(bf[jj][0], bf[jj][1], bf[jj][2], bf[jj][3], bd);
            }
            #pragma unroll
            for (int i = 0; i < 2; ++i) {
                #pragma unroll
                for (int j = 0; j < 8; ++j) {
                    const int jj = j >> 1, sel = j & 1;
                    MMA16816(c[i][j], af[i], bf[jj][sel], bf[jj][sel + 2]);
                }
            }
        }
    }

    // ---------------- fused epilogue ----------------
    if (z == 2) {
        #pragma unroll
        for (int i = 0; i < 2; ++i) {
            #pragma unroll
            for (int j = 0; j < 8; ++j) {
                int row = m0 + warpM * 32 + i * 16 + (lane >> 2);
                int col = n0 + warpN * 64 + j * 8 + (lane & 3) * 2;
                float b0v = bias[col], b1v = bias[col + 1];
                *(__half2*)&Ch[(size_t)row * DIM + col] =
                    __floats2half2_rn(c[i][j][0] + b0v, c[i][j][1] + b1v);
                *(__half2*)&Ch[(size_t)(row + 8) * DIM + col] =
                    __floats2half2_rn(c[i][j][2] + b0v, c[i][j][3] + b1v);
            }
        }
    } else {
        const float scale = (z == 0) ? QSCALE : 1.0f;
        #pragma unroll
        for (int i = 0; i < 2; ++i) {
            int rowA = m0 + warpM * 32 + i * 16 + (lane >> 2);
            int rowB = rowA + 8;
            int pA0 = pos[2 * rowA], pA1 = pos[2 * rowA + 1];
            int pB0 = pos[2 * rowB], pB1 = pos[2 * rowB + 1];
            #pragma unroll
            for (int jj = 0; jj < 4; ++jj) {
                const int j = (jj < 2) ? jj : jj + 2;   // 0,1,4,5
                const int half = (j >= 4);
                int col = n0 + warpN * 64 + j * 8 + (lane & 3) * 2;
                int f0 = (j & 1) * 8 + (lane & 3) * 2;
                int pA = half ? pA1 : pA0;
                int pB = half ? pB1 : pB0;
                float cA0 = g_cosT[pA * 16 + f0], cA1 = g_cosT[pA * 16 + f0 + 1];
                float sA0 = g_sinT[pA * 16 + f0], sA1 = g_sinT[pA * 16 + f0 + 1];
                float cB0 = g_cosT[pB * 16 + f0], cB1 = g_cosT[pB * 16 + f0 + 1];
                float sB0 = g_sinT[pB * 16 + f0], sB1 = g_sinT[pB * 16 + f0 + 1];
                float b1x = bias[col], b1y = bias[col + 1];
                float b2x = bias[col + 16], b2y = bias[col + 17];

                {
                    float v1x = c[i][j][0] + b1x,     v1y = c[i][j][1] + b1y;
                    float v2x = c[i][j + 2][0] + b2x, v2y = c[i][j + 2][1] + b2y;
                    *(__half2*)&Ch[(size_t)rowA * DIM + col] =
                        __floats2half2_rn((v1x * cA0 - v2x * sA0) * scale,
                                          (v1y * cA1 - v2y * sA1) * scale);
                    *(__half2*)&Ch[(size_t)rowA * DIM + col + 16] =
                        __floats2half2_rn((v2x * cA0 + v1x * sA0) * scale,
                                          (v2y * cA1 + v1y * sA1) * scale);
                }
                {
                    float v1x = c[i][j][2] + b1x,     v1y = c[i][j][3] + b1y;
                    float v2x = c[i][j + 2][2] + b2x, v2y = c[i][j + 2][3] + b2y;
                    *(__half2*)&Ch[(size_t)rowB * DIM + col] =
                        __floats2half2_rn((v1x * cB0 - v2x * sB0) * scale,
                                          (v1y * cB1 - v2y * sB1) * scale);
                    *(__half2*)&Ch[(size_t)rowB * DIM + col + 16] =
                        __floats2half2_rn((v2x * cB0 + v1x * sB0) * scale,
                                          (v2y * cB1 + v1y * sB1) * scale);
                }
            }
        }
    }
}

// ---------------- final output GEMM: out = Aoh @ WTo^T + bo (fp32) ----------------
__global__ __launch_bounds__(256, 2) void out_gemm_kernel(
    const __half* __restrict__ A, const __half* __restrict__ B,
    const float* __restrict__ bias, float* __restrict__ Cf)
{
    extern __shared__ char sm[];
    const uint32_t sbase = smem_u32(sm);
    const int tid  = threadIdx.x;
    const int lane = tid & 31;
    const int wid  = tid >> 5;
    const int warpM = wid & 3;
    const int warpN = wid >> 2;
    const int m0 = blockIdx.y * 128;
    const int n0 = blockIdx.x * 128;

    float c[2][8][4];
    #pragma unroll
    for (int i = 0; i < 2; ++i)
        #pragma unroll
        for (int j = 0; j < 8; ++j)
            #pragma unroll
            for (int q = 0; q < 4; ++q) c[i][j][q] = 0.f;

    const int rr0 = tid >> 3;
    const int cc  = tid & 7;

    auto issue_stage = [&](int kt, int s) {
        #pragma unroll
        for (int i = 0; i < 4; ++i) {
            int r = rr0 + i * 32;
            uint32_t sw = (uint32_t)(r * 128 + ((cc ^ (r & 7)) << 4));
            uint32_t da = sbase + s * STAGE_B + sw;
            uint32_t db = da + AS_BYTES;
            const char* ga = (const char*)(A + (size_t)(m0 + r) * DIM + kt * 64 + cc * 8);
            const char* gb = (const char*)(B + (size_t)(n0 + r) * DIM + kt * 64 + cc * 8);
            CP_ASYNC16(da, ga);
            CP_ASYNC16(db, gb);
        }
        CP_COMMIT();
    };

    const int lrow8 = ((lane >> 3) & 1) * 8 + (lane & 7);
    const int lcol16 = (lane >> 4) * 16;

    issue_stage(0, 0);

    for (int kt = 0; kt < NKT; ++kt) {
        CP_WAIT(0);
        __syncthreads();
        if (kt + 1 < NKT) issue_stage(kt + 1, (kt + 1) & 1);

        const uint32_t ab = sbase + (kt & 1) * STAGE_B;
        const uint32_t bb = ab + AS_BYTES;

        #pragma unroll
        for (int ks = 0; ks < 4; ++ks) {
            const int kb = ks * 32;
            uint32_t af[2][4];
            #pragma unroll
            for (int i = 0; i < 2; ++i) {
                int row = warpM * 32 + i * 16 + lrow8;
                int col = kb + lcol16;
                uint32_t ad = ab + row * 128 + ((((col >> 4) ^ (row & 7)) & 7) << 4);
                LDSM_X4(af[i][0], af[i][1], af[i][2], af[i][3], ad);
            }
            uint32_t bf[4][4];
            #pragma unroll
            for (int jj = 0; jj < 4; ++jj) {
                int nrow = warpN * 64 + jj * 16 + lrow8;
                int col = kb + lcol16;
                uint32_t bd = bb + nrow * 128 + ((((col >> 4) ^ (nrow & 7)) & 7) << 4);
                LDSM_X4(bf[jj][0], bf[jj][1], bf[jj][2], bf[jj][3], bd);
            }
            #pragma unroll
            for (int i = 0; i < 2; ++i) {
                #pragma unroll
                for (int j = 0; j < 8; ++j) {
                    const int jj = j >> 1, sel = j & 1;
                    MMA16816(c[i][j], af[i], bf[jj][sel], bf[jj][sel + 2]);
                }
            }
        }
    }

    #pragma unroll
    for (int i = 0; i < 2; ++i) {
        #pragma unroll
        for (int j = 0; j < 8; ++j) {
            int row = m0 + warpM * 32 + i * 16 + (lane >> 2);
            int col = n0 + warpN * 64 + j * 8 + (lane & 3) * 2;
            float b0v = bias[col], b1v = bias[col + 1];
            float2 o0 = {c[i][j][0] + b0v, c[i][j][1] + b1v};
            float2 o1 = {c[i][j][2] + b0v, c[i][j][3] + b1v};
            *(float2*)&Cf[(size_t)row * DIM + col] = o0;
            *(float2*)&Cf[(size_t)(row + 8) * DIM + col] = o1;
        }
    }
}

// ---------------- fp16 tensor-core flash attention: 128q x 64kv, 3-stage pipeline ----------------
// stage: K (8K) + V (8K) = 16 KB, 3 stages; Q tile 16 KB.
#define FS_STAGE 16384
#define FS_NSTG 3
#define FS_Q_OFF (FS_NSTG * FS_STAGE)           // 49152
#define FS_SMEM (FS_Q_OFF + 16384)              // 65536
#define FS_NT (SEQ / 64)                        // 16

__global__ __launch_bounds__(256) void flash16_kernel(
    const __half* __restrict__ Qh, const __half* __restrict__ Kh,
    const __half* __restrict__ Vh, __half* __restrict__ Ao)
{
    extern __shared__ char sm[];
    const uint32_t sb = smem_u32(sm);
    const int tid  = threadIdx.x;
    const int lane = tid & 31;
    const int wid  = tid >> 5;
    const int qb   = blockIdx.x * 128;
    const int h    = blockIdx.y;
    const int b    = blockIdx.z;
    const size_t qrow0 = (size_t)b * SEQ + qb;
    const int colh = h * DH;

    const int lrow8  = ((lane >> 3) & 1) * 8 + (lane & 7);
    const int lcol16 = (lane >> 4) * 16;

    // Q tile load (its own group, oldest)
    #pragma unroll
    for (int i = 0; i < 4; ++i) {
        int idx = tid + i * 256;
        int r = idx >> 3, c = idx & 7;
        uint32_t sw = (uint32_t)(r * 128 + ((c ^ (r & 7)) << 4));
        size_t goff = (qrow0 + r) * DIM + colh + c * 8;
        CP_ASYNC16(sb + FS_Q_OFF + sw, (const char*)(Qh + goff));
    }
    CP_COMMIT();

    auto issue_kv = [&](int kt, int s) {
        const size_t rowbase = (size_t)b * SEQ + (size_t)kt * 64;
        const uint32_t st = sb + s * FS_STAGE;
        #pragma unroll
        for (int i = 0; i < 2; ++i) {
            int idx = tid + i * 256;
            int r = idx >> 3, c = idx & 7;
            uint32_t sw = (uint32_t)(r * 128 + ((c ^ (r & 7)) << 4));
            size_t goff = (rowbase + r) * DIM + colh + c * 8;
            CP_ASYNC16(st + sw,        (const char*)(Kh + goff));
            CP_ASYNC16(st + 8192 + sw, (const char*)(Vh + goff));
        }
        CP_COMMIT();
    };

    // prologue: 2 kv stages in flight
    issue_kv(0, 0);
    issue_kv(1, 1);
    CP_WAIT(1);                      // Q + kv0 complete; kv1 may be pending
    __syncthreads();

    uint32_t qhf[4][4];
    #pragma unroll
    for (int kc = 0; kc < 4; ++kc) {
        int row = wid * 16 + lrow8;
        int col = kc * 32 + lcol16;
        uint32_t ad = sb + FS_Q_OFF + row * 128 + ((((col >> 4) ^ (row & 7)) & 7) << 4);
        LDSM_X4(qhf[kc][0], qhf[kc][1], qhf[kc][2], qhf[kc][3], ad);
    }

    float o[8][4];
    #pragma unroll
    for (int i = 0; i < 8; ++i)
        #pragma unroll
        for (int q = 0; q < 4; ++q) o[i][q] = 0.f;
    float m0 = -1e30f, m1 = -1e30f, l0 = 0.f, l1 = 0.f;   // l: per-thread partials

    int stg = 0;
    for (int kt = 0; kt < FS_NT; ++kt) {
        if (kt) {
            if (kt >= FS_NT - 2) CP_WAIT(0);
            else                 CP_WAIT(1);
            __syncthreads();
        }
        if (kt + 2 < FS_NT) {
            int s2 = stg + 2;
            if (s2 >= FS_NSTG) s2 -= FS_NSTG;
            issue_kv(kt + 2, s2);
        }

        const uint32_t kb = sb + stg * FS_STAGE;
        const uint32_t vb = kb + 8192;
        if (++stg == FS_NSTG) stg = 0;

        float s[8][4];
        #pragma unroll
        for (int i = 0; i < 8; ++i)
            #pragma unroll
            for (int q = 0; q < 4; ++q) s[i][q] = 0.f;

        // S = Q K^T : single pass (Qh*Kh)
        #pragma unroll
        for (int kc = 0; kc < 4; ++kc) {
            const int col = kc * 32 + lcol16;
            #pragma unroll
            for (int nb2 = 0; nb2 < 4; ++nb2) {
                int row = nb2 * 16 + lrow8;
                uint32_t ad = kb + row * 128 + ((((col >> 4) ^ (row & 7)) & 7) << 4);
                uint32_t f0, f1, f2, f3;
                LDSM_X4(f0, f1, f2, f3, ad);
                MMA16816(s[2 * nb2],     qhf[kc], f0, f2);
                MMA16816(s[2 * nb2 + 1], qhf[kc], f1, f3);
            }
        }

        float mx0 = -1e30f, mx1 = -1e30f;
        #pragma unroll
        for (int nb = 0; nb < 8; ++nb) {
            mx0 = fmaxf(mx0, fmaxf(s[nb][0], s[nb][1]));
            mx1 = fmaxf(mx1, fmaxf(s[nb][2], s[nb][3]));
        }
        mx0 = fmaxf(mx0, __shfl_xor_sync(0xffffffffu, mx0, 1));
        mx0 = fmaxf(mx0, __shfl_xor_sync(0xffffffffu, mx0, 2));
        mx1 = fmaxf(mx1, __shfl_xor_sync(0xffffffffu, mx1, 1));
        mx1 = fmaxf(mx1, __shfl_xor_sync(0xffffffffu, mx1, 2));
        float mn0 = fmaxf(m0, mx0), mn1 = fmaxf(m1, mx1);
        float cr0 = ex2f(m0 - mn0), cr1 = ex2f(m1 - mn1);
        m0 = mn0; m1 = mn1;

        float ls0 = 0.f, ls1 = 0.f;
        uint32_t a[4][4];
        #pragma unroll
        for (int nb = 0; nb < 8; ++nb) {
            float p0 = ex2f(s[nb][0] - mn0);
            float p1 = ex2f(s[nb][1] - mn0);
            float p2 = ex2f(s[nb][2] - mn1);
            float p3 = ex2f(s[nb][3] - mn1);
            ls0 += p0 + p1;
            ls1 += p2 + p3;
            __half2 h01 = __floats2half2_rn(p0, p1);
            __half2 h23 = __floats2half2_rn(p2, p3);
            int kc = nb >> 1;
            if ((nb & 1) == 0) {
                a[kc][0] = *(uint32_t*)&h01;
                a[kc][1] = *(uint32_t*)&h23;
            } else {
                a[kc][2] = *(uint32_t*)&h01;
                a[kc][3] = *(uint32_t*)&h23;
            }
        }
        // per-thread l partials (corr uniform across lane quad -> exact)
        l0 = l0 * cr0 + ls0;
        l1 = l1 * cr1 + ls1;
        #pragma unroll
        for (int db = 0; db < 8; ++db) {
            o[db][0] *= cr0; o[db][1] *= cr0;
            o[db][2] *= cr1; o[db][3] *= cr1;
        }

        // O += P V (single pass, fp16 V)
        #pragma unroll
        for (int kc = 0; kc < 4; ++kc) {
            int row = kc * 16 + lrow8;
            #pragma unroll
            for (int db2 = 0; db2 < 4; ++db2) {
                int col = db2 * 32 + lcol16;
                uint32_t ad = vb + row * 128 + ((((col >> 4) ^ (row & 7)) & 7) << 4);
                uint32_t f0, f1, f2, f3;
                LDSM_X4_T(f0, f1, f2, f3, ad);
                MMA16816(o[2 * db2],     a[kc], f0, f1);
                MMA16816(o[2 * db2 + 1], a[kc], f2, f3);
            }
        }
    }

    // deferred cross-lane l reduction
    l0 += __shfl_xor_sync(0xffffffffu, l0, 1);
    l0 += __shfl_xor_sync(0xffffffffu, l0, 2);
    l1 += __shfl_xor_sync(0xffffffffu, l1, 1);
    l1 += __shfl_xor_sync(0xffffffffu, l1, 2);

    float inv0 = 1.0f / l0, inv1 = 1.0f / l1;
    size_t r0 = qrow0 + wid * 16 + (lane >> 2);
    size_t r1 = r0 + 8;
    int cb = colh + (lane & 3) * 2;
    #pragma unroll
    for (int db = 0; db < 8; ++db) {
        __half2 w0 = __floats2half2_rn(o[db][0] * inv0, o[db][1] * inv0);
        __half2 w1 = __floats2half2_rn(o[db][2] * inv1, o[db][3] * inv1);
        *(__half2*)&Ao[r0 * DIM + cb + db * 8] = w0;
        *(__half2*)&Ao[r1 * DIM + cb + db * 8] = w1;
    }
}

// ---------------- launch ----------------
extern "C" void kernel_launch(void* const* d_in, const int* in_sizes, int n_in,
                              void* d_out, int out_size) {
    const float* x      = (const float*)d_in[0];
    const float* y      = (const float*)d_in[1];
    const int*   pos_q  = (const int*)d_in[2];
    const int*   pos_kv = (const int*)d_in[3];
    const float* Wq = (const float*)d_in[4];
    const float* bq = (const float*)d_in[5];
    const float* Wk = (const float*)d_in[6];
    const float* bk = (const float*)d_in[7];
    const float* Wv = (const float*)d_in[8];
    const float* bv = (const float*)d_in[9];
    const float* Wo = (const float*)d_in[10];
    const float* bo = (const float*)d_in[11];
    float* out = (float*)d_out;

    __half *Xh, *Yh, *WTq, *WTk, *WTv, *WTo;
    __half *Qhp, *Khp, *Vhp, *Aohp;
    cudaGetSymbolAddress((void**)&Xh, g_Xh);
    cudaGetSymbolAddress((void**)&Yh, g_Yh);
    cudaGetSymbolAddress((void**)&WTq, g_WTq);
    cudaGetSymbolAddress((void**)&WTk, g_WTk);
    cudaGetSymbolAddress((void**)&WTv, g_WTv);
    cudaGetSymbolAddress((void**)&WTo, g_WTo);
    cudaGetSymbolAddress((void**)&Qhp, g_Qh);
    cudaGetSymbolAddress((void**)&Khp, g_Kh);
    cudaGetSymbolAddress((void**)&Vhp, g_Vh);
    cudaGetSymbolAddress((void**)&Aohp, g_Aoh);

    cudaFuncSetAttribute(qkv_gemm_kernel, cudaFuncAttributeMaxDynamicSharedMemorySize, GEMM_SMEM);
    cudaFuncSetAttribute(out_gemm_kernel, cudaFuncAttributeMaxDynamicSharedMemorySize, GEMM_SMEM);
    cudaFuncSetAttribute(flash16_kernel, cudaFuncAttributeMaxDynamicSharedMemorySize, FS_SMEM);

    const int n4 = (ROWS * DIM) / 4;
    f2h2_kernel<<<dim3((n4 + 255) / 256, 2), 256>>>(x, y, Xh, Yh, n4);

    transpose4_kernel<<<dim3(DIM / 32, DIM / 32, 4), dim3(32, 8)>>>(
        Wq, Wk, Wv, Wo, WTq, WTk, WTv, WTo);

    qkv_gemm_kernel<<<dim3(DIM / 128, ROWS / 128, 3), 256, GEMM_SMEM>>>(
        Xh, Yh, WTq, WTk, WTv, bq, bk, bv, pos_q, pos_kv,
        Qhp, Khp, Vhp);

    flash16_kernel<<<dim3(SEQ / 128, HEADS, BATCH), 256, FS_SMEM>>>(
        Qhp, Khp, Vhp, Aohp);

    out_gemm_kernel<<<dim3(DIM / 128, ROWS / 128), 256, GEMM_SMEM>>>(Aohp, WTo, bo, out);
}

// round 15
// speedup vs baseline: 1.0299x; 1.0061x over previous
#include <cuda_runtime.h>
#include <cuda_fp16.h>
#include <math.h>
#include <stdint.h>

#define HEADS 12
#define DH 64
#define DIM 768
#define BATCH 8
#define SEQ 1024
#define ROWS (BATCH * SEQ)   // 8192

#define QSCALE 0.1803368801111204f   // 0.125 * log2(e)

// ---------------- scratch ----------------
__device__ __half g_Xh[ROWS * DIM];
__device__ __half g_Yh[ROWS * DIM];
__device__ __half g_WTq[DIM * DIM];
__device__ __half g_WTk[DIM * DIM];
__device__ __half g_WTv[DIM * DIM];
__device__ __half g_WTo[DIM * DIM];
__device__ __half g_Qh[ROWS * DIM];
__device__ __half g_Kh[ROWS * DIM];
__device__ __half g_Vh[ROWS * DIM];
__device__ __half g_Aoh[ROWS * DIM];
__device__ float g_cosT[512];
__device__ float g_sinT[512];

// ---------------- helpers ----------------
__device__ __forceinline__ uint32_t smem_u32(const void* p) {
    uint32_t a;
    asm("{ .reg .u64 t; cvta.to.shared.u64 t, %1; cvt.u32.u64 %0, t; }" : "=r"(a) : "l"(p));
    return a;
}
__device__ __forceinline__ float ex2f(float x) {
    float y;
    asm("ex2.approx.ftz.f32 %0, %1;" : "=f"(y) : "f"(x));
    return y;
}

#define LDSM_X4(r0, r1, r2, r3, addr)                                          \
    asm volatile("ldmatrix.sync.aligned.m8n8.x4.shared.b16 {%0,%1,%2,%3}, [%4];" \
                 : "=r"(r0), "=r"(r1), "=r"(r2), "=r"(r3) : "r"(addr))

#define LDSM_X4_T(r0, r1, r2, r3, addr)                                        \
    asm volatile("ldmatrix.sync.aligned.m8n8.x4.trans.shared.b16 {%0,%1,%2,%3}, [%4];" \
                 : "=r"(r0), "=r"(r1), "=r"(r2), "=r"(r3) : "r"(addr))

#define MMA16816(c, a, b0, b1)                                                 \
    asm volatile("mma.sync.aligned.m16n8k16.row.col.f32.f16.f16.f32 "          \
                 "{%0,%1,%2,%3}, {%4,%5,%6,%7}, {%8,%9}, {%0,%1,%2,%3};"       \
                 : "+f"((c)[0]), "+f"((c)[1]), "+f"((c)[2]), "+f"((c)[3])      \
                 : "r"((a)[0]), "r"((a)[1]), "r"((a)[2]), "r"((a)[3]),         \
                   "r"(b0), "r"(b1))

#define CP_ASYNC16(dst, src)                                                   \
    asm volatile("cp.async.cg.shared.global [%0], [%1], 16;" :: "r"(dst), "l"(src))
#define CP_COMMIT() asm volatile("cp.async.commit_group;" ::: "memory")
#define CP_WAIT(n)  asm volatile("cp.async.wait_group %0;" :: "n"(n) : "memory")

// ---------------- float -> half (x and y in one launch) ----------------
__global__ void f2h2_kernel(const float* __restrict__ x, const float* __restrict__ y,
                            __half* __restrict__ Xh, __half* __restrict__ Yh, int n4) {
    int i = blockIdx.x * blockDim.x + threadIdx.x;
    if (i >= n4) return;
    const float* src = blockIdx.y ? y : x;
    __half* dst = blockIdx.y ? Yh : Xh;
    float4 v = ((const float4*)src)[i];
    __half2 lo = __floats2half2_rn(v.x, v.y);
    __half2 hi = __floats2half2_rn(v.z, v.w);
    uint2 o;
    o.x = *(uint32_t*)&lo;
    o.y = *(uint32_t*)&hi;
    ((uint2*)dst)[i] = o;
}

// ---------------- 4 weight transposes + RoPE table init in one launch ----------------
__global__ void transpose4_kernel(const float* __restrict__ Wq, const float* __restrict__ Wk,
                                  const float* __restrict__ Wv, const float* __restrict__ Wo,
                                  __half* __restrict__ Tq, __half* __restrict__ Tk,
                                  __half* __restrict__ Tv, __half* __restrict__ To) {
    const int z = blockIdx.z;
    if (z == 0 && blockIdx.x == 0 && blockIdx.y == 0) {
        int t = threadIdx.y * 32 + threadIdx.x;
        #pragma unroll
        for (int rep = 0; rep < 2; ++rep) {
            int i = t + rep * 256;
            int p = i >> 4;
            int f = i & 15;
            double inv = pow(100.0, -((double)(2 * f)) / 32.0);
            double fr = (double)p * inv;
            g_cosT[i] = (float)cos(fr);
            g_sinT[i] = (float)sin(fr);
        }
    }
    const float* W = (z == 0) ? Wq : (z == 1) ? Wk : (z == 2) ? Wv : Wo;
    __half* T = (z == 0) ? Tq : (z == 1) ? Tk : (z == 2) ? Tv : To;
    __shared__ float tile[32][33];
    int bx = blockIdx.x * 32;
    int by = blockIdx.y * 32;
    int x = threadIdx.x, y = threadIdx.y;
    #pragma unroll
    for (int j = 0; j < 4; ++j)
        tile[y + 8 * j][x] = W[(by + y + 8 * j) * DIM + bx + x];
    __syncthreads();
    #pragma unroll
    for (int j = 0; j < 4; ++j)
        T[(size_t)(bx + y + 8 * j) * DIM + by + x] = __float2half(tile[x][y + 8 * j]);
}

// ---------------- GEMM tile constants (3-stage pipeline) ----------------
#define NKT (DIM / 64)
#define AS_BYTES (128 * 128)
#define STAGE_B (2 * AS_BYTES)
#define GEMM_NSTG 3
#define GEMM_SMEM (GEMM_NSTG * STAGE_B)   // 98304

// ---------------- fused Q/K/V projection GEMM (one launch, z picks mode) ----------------
__global__ __launch_bounds__(256, 2) void qkv_gemm_kernel(
    const __half* __restrict__ Xh, const __half* __restrict__ Yh,
    const __half* __restrict__ WTq, const __half* __restrict__ WTk, const __half* __restrict__ WTv,
    const float* __restrict__ bq, const float* __restrict__ bk, const float* __restrict__ bv,
    const int* __restrict__ pos_q, const int* __restrict__ pos_kv,
    __half* __restrict__ Qh, __half* __restrict__ Kh, __half* __restrict__ Vh)
{
    extern __shared__ char sm[];
    const uint32_t sbase = smem_u32(sm);
    const int z = blockIdx.z;
    const __half* A = (z == 0) ? Xh : Yh;
    const __half* B = (z == 0) ? WTq : (z == 1) ? WTk : WTv;
    const float* bias = (z == 0) ? bq : (z == 1) ? bk : bv;
    const int* pos = (z == 0) ? pos_q : pos_kv;
    __half* Ch = (z == 0) ? Qh : (z == 1) ? Kh : Vh;

    const int tid  = threadIdx.x;
    const int lane = tid & 31;
    const int wid  = tid >> 5;
    const int warpM = wid & 3;
    const int warpN = wid >> 2;
    const int m0 = blockIdx.y * 128;
    const int n0 = blockIdx.x * 128;

    float c[2][8][4];
    #pragma unroll
    for (int i = 0; i < 2; ++i)
        #pragma unroll
        for (int j = 0; j < 8; ++j)
            #pragma unroll
            for (int q = 0; q < 4; ++q) c[i][j][q] = 0.f;

    const int rr0 = tid >> 3;
    const int cc  = tid & 7;

    auto issue_stage = [&](int kt, int s) {
        #pragma unroll
        for (int i = 0; i < 4; ++i) {
            int r = rr0 + i * 32;
            uint32_t sw = (uint32_t)(r * 128 + ((cc ^ (r & 7)) << 4));
            uint32_t da = sbase + s * STAGE_B + sw;
            uint32_t db = da + AS_BYTES;
            const char* ga = (const char*)(A + (size_t)(m0 + r) * DIM + kt * 64 + cc * 8);
            const char* gb = (const char*)(B + (size_t)(n0 + r) * DIM + kt * 64 + cc * 8);
            CP_ASYNC16(da, ga);
            CP_ASYNC16(db, gb);
        }
        CP_COMMIT();
    };

    const int lrow8 = ((lane >> 3) & 1) * 8 + (lane & 7);
    const int lcol16 = (lane >> 4) * 16;

    issue_stage(0, 0);
    issue_stage(1, 1);

    int stg = 0;
    for (int kt = 0; kt < NKT; ++kt) {
        if (kt == NKT - 1) CP_WAIT(0);
        else               CP_WAIT(1);
        __syncthreads();
        if (kt + 2 < NKT) {
            int s2 = stg + 2;
            if (s2 >= GEMM_NSTG) s2 -= GEMM_NSTG;
            issue_stage(kt + 2, s2);
        }

        const uint32_t ab = sbase + stg * STAGE_B;
        const uint32_t bb = ab + AS_BYTES;
        if (++stg == GEMM_NSTG) stg = 0;

        #pragma unroll
        for (int ks = 0; ks < 4; ++ks) {
            const int kb = ks * 32;
            uint32_t af[2][4];
            #pragma unroll
            for (int i = 0; i < 2; ++i) {
                int row = warpM * 32 + i * 16 + lrow8;
                int col = kb + lcol16;
                uint32_t ad = ab + row * 128 + ((((col >> 4) ^ (row & 7)) & 7) << 4);
                LDSM_X4(af[i][0], af[i][1], af[i][2], af[i][3], ad);
            }
            uint32_t bf[4][4];
            #pragma unroll
            for (int jj = 0; jj < 4; ++jj) {
                int nrow = warpN * 64 + jj * 16 + lrow8;
                int col = kb + lcol16;
                uint32_t bd = bb + nrow * 128 + ((((col >> 4) ^ (nrow & 7)) & 7) << 4);
                LDSM_X4(bf[jj][0], bf[jj][1], bf[jj][2], bf[jj][3], bd);
            }
            #pragma unroll
            for (int i = 0; i < 2; ++i) {
                #pragma unroll
                for (int j = 0; j < 8; ++j) {
                    const int jj = j >> 1, sel = j & 1;
                    MMA16816(c[i][j], af[i], bf[jj][sel], bf[jj][sel + 2]);
                }
            }
        }
    }

    // ---------------- fused epilogue ----------------
    if (z == 2) {
        #pragma unroll
        for (int i = 0; i < 2; ++i) {
            #pragma unroll
            for (int j = 0; j < 8; ++j) {
                int row = m0 + warpM * 32 + i * 16 + (lane >> 2);
                int col = n0 + warpN * 64 + j * 8 + (lane & 3) * 2;
                float b0v = bias[col], b1v = bias[col + 1];
                *(__half2*)&Ch[(size_t)row * DIM + col] =
                    __floats2half2_rn(c[i][j][0] + b0v, c[i][j][1] + b1v);
                *(__half2*)&Ch[(size_t)(row + 8) * DIM + col] =
                    __floats2half2_rn(c[i][j][2] + b0v, c[i][j][3] + b1v);
            }
        }
    } else {
        const float scale = (z == 0) ? QSCALE : 1.0f;
        #pragma unroll
        for (int i = 0; i < 2; ++i) {
            int rowA = m0 + warpM * 32 + i * 16 + (lane >> 2);
            int rowB = rowA + 8;
            int pA0 = pos[2 * rowA], pA1 = pos[2 * rowA + 1];
            int pB0 = pos[2 * rowB], pB1 = pos[2 * rowB + 1];
            #pragma unroll
            for (int jj = 0; jj < 4; ++jj) {
                const int j = (jj < 2) ? jj : jj + 2;   // 0,1,4,5
                const int half = (j >= 4);
                int col = n0 + warpN * 64 + j * 8 + (lane & 3) * 2;
                int f0 = (j & 1) * 8 + (lane & 3) * 2;
                int pA = half ? pA1 : pA0;
                int pB = half ? pB1 : pB0;
                float cA0 = g_cosT[pA * 16 + f0], cA1 = g_cosT[pA * 16 + f0 + 1];
                float sA0 = g_sinT[pA * 16 + f0], sA1 = g_sinT[pA * 16 + f0 + 1];
                float cB0 = g_cosT[pB * 16 + f0], cB1 = g_cosT[pB * 16 + f0 + 1];
                float sB0 = g_sinT[pB * 16 + f0], sB1 = g_sinT[pB * 16 + f0 + 1];
                float b1x = bias[col], b1y = bias[col + 1];
                float b2x = bias[col + 16], b2y = bias[col + 17];

                {
                    float v1x = c[i][j][0] + b1x,     v1y = c[i][j][1] + b1y;
                    float v2x = c[i][j + 2][0] + b2x, v2y = c[i][j + 2][1] + b2y;
                    *(__half2*)&Ch[(size_t)rowA * DIM + col] =
                        __floats2half2_rn((v1x * cA0 - v2x * sA0) * scale,
                                          (v1y * cA1 - v2y * sA1) * scale);
                    *(__half2*)&Ch[(size_t)rowA * DIM + col + 16] =
                        __floats2half2_rn((v2x * cA0 + v1x * sA0) * scale,
                                          (v2y * cA1 + v1y * sA1) * scale);
                }
                {
                    float v1x = c[i][j][2] + b1x,     v1y = c[i][j][3] + b1y;
                    float v2x = c[i][j + 2][2] + b2x, v2y = c[i][j + 2][3] + b2y;
                    *(__half2*)&Ch[(size_t)rowB * DIM + col] =
                        __floats2half2_rn((v1x * cB0 - v2x * sB0) * scale,
                                          (v1y * cB1 - v2y * sB1) * scale);
                    *(__half2*)&Ch[(size_t)rowB * DIM + col + 16] =
                        __floats2half2_rn((v2x * cB0 + v1x * sB0) * scale,
                                          (v2y * cB1 + v1y * sB1) * scale);
                }
            }
        }
    }
}

// ---------------- final output GEMM: out = Aoh @ WTo^T + bo (fp32) ----------------
__global__ __launch_bounds__(256, 2) void out_gemm_kernel(
    const __half* __restrict__ A, const __half* __restrict__ B,
    const float* __restrict__ bias, float* __restrict__ Cf)
{
    extern __shared__ char sm[];
    const uint32_t sbase = smem_u32(sm);
    const int tid  = threadIdx.x;
    const int lane = tid & 31;
    const int wid  = tid >> 5;
    const int warpM = wid & 3;
    const int warpN = wid >> 2;
    const int m0 = blockIdx.y * 128;
    const int n0 = blockIdx.x * 128;

    float c[2][8][4];
    #pragma unroll
    for (int i = 0; i < 2; ++i)
        #pragma unroll
        for (int j = 0; j < 8; ++j)
            #pragma unroll
            for (int q = 0; q < 4; ++q) c[i][j][q] = 0.f;

    const int rr0 = tid >> 3;
    const int cc  = tid & 7;

    auto issue_stage = [&](int kt, int s) {
        #pragma unroll
        for (int i = 0; i < 4; ++i) {
            int r = rr0 + i * 32;
            uint32_t sw = (uint32_t)(r * 128 + ((cc ^ (r & 7)) << 4));
            uint32_t da = sbase + s * STAGE_B + sw;
            uint32_t db = da + AS_BYTES;
            const char* ga = (const char*)(A + (size_t)(m0 + r) * DIM + kt * 64 + cc * 8);
            const char* gb = (const char*)(B + (size_t)(n0 + r) * DIM + kt * 64 + cc * 8);
            CP_ASYNC16(da, ga);
            CP_ASYNC16(db, gb);
        }
        CP_COMMIT();
    };

    const int lrow8 = ((lane >> 3) & 1) * 8 + (lane & 7);
    const int lcol16 = (lane >> 4) * 16;

    issue_stage(0, 0);
    issue_stage(1, 1);

    int stg = 0;
    for (int kt = 0; kt < NKT; ++kt) {
        if (kt == NKT - 1) CP_WAIT(0);
        else               CP_WAIT(1);
        __syncthreads();
        if (kt + 2 < NKT) {
            int s2 = stg + 2;
            if (s2 >= GEMM_NSTG) s2 -= GEMM_NSTG;
            issue_stage(kt + 2, s2);
        }

        const uint32_t ab = sbase + stg * STAGE_B;
        const uint32_t bb = ab + AS_BYTES;
        if (++stg == GEMM_NSTG) stg = 0;

        #pragma unroll
        for (int ks = 0; ks < 4; ++ks) {
            const int kb = ks * 32;
            uint32_t af[2][4];
            #pragma unroll
            for (int i = 0; i < 2; ++i) {
                int row = warpM * 32 + i * 16 + lrow8;
                int col = kb + lcol16;
                uint32_t ad = ab + row * 128 + ((((col >> 4) ^ (row & 7)) & 7) << 4);
                LDSM_X4(af[i][0], af[i][1], af[i][2], af[i][3], ad);
            }
            uint32_t bf[4][4];
            #pragma unroll
            for (int jj = 0; jj < 4; ++jj) {
                int nrow = warpN * 64 + jj * 16 + lrow8;
                int col = kb + lcol16;
                uint32_t bd = bb + nrow * 128 + ((((col >> 4) ^ (nrow & 7)) & 7) << 4);
                LDSM_X4(bf[jj][0], bf[jj][1], bf[jj][2], bf[jj][3], bd);
            }
            #pragma unroll
            for (int i = 0; i < 2; ++i) {
                #pragma unroll
                for (int j = 0; j < 8; ++j) {
                    const int jj = j >> 1, sel = j & 1;
                    MMA16816(c[i][j], af[i], bf[jj][sel], bf[jj][sel + 2]);
                }
            }
        }
    }

    #pragma unroll
    for (int i = 0; i < 2; ++i) {
        #pragma unroll
        for (int j = 0; j < 8; ++j) {
            int row = m0 + warpM * 32 + i * 16 + (lane >> 2);
            int col = n0 + warpN * 64 + j * 8 + (lane & 3) * 2;
            float b0v = bias[col], b1v = bias[col + 1];
            float2 o0 = {c[i][j][0] + b0v, c[i][j][1] + b1v};
            float2 o1 = {c[i][j][2] + b0v, c[i][j][3] + b1v};
            *(float2*)&Cf[(size_t)row * DIM + col] = o0;
            *(float2*)&Cf[(size_t)(row + 8) * DIM + col] = o1;
        }
    }
}

// ---------------- fp16 tensor-core flash attention: 128q x 64kv, 3-stage pipeline ----------------
#define FS_STAGE 16384
#define FS_NSTG 3
#define FS_Q_OFF (FS_NSTG * FS_STAGE)           // 49152
#define FS_SMEM (FS_Q_OFF + 16384)              // 65536
#define FS_NT (SEQ / 64)                        // 16

__global__ __launch_bounds__(256, 2) void flash16_kernel(
    const __half* __restrict__ Qh, const __half* __restrict__ Kh,
    const __half* __restrict__ Vh, __half* __restrict__ Ao)
{
    extern __shared__ char sm[];
    const uint32_t sb = smem_u32(sm);
    const int tid  = threadIdx.x;
    const int lane = tid & 31;
    const int wid  = tid >> 5;
    const int qb   = blockIdx.x * 128;
    const int h    = blockIdx.y;
    const int b    = blockIdx.z;
    const size_t qrow0 = (size_t)b * SEQ + qb;
    const int colh = h * DH;

    const int lrow8  = ((lane >> 3) & 1) * 8 + (lane & 7);
    const int lcol16 = (lane >> 4) * 16;

    // Q tile load (its own group, oldest)
    #pragma unroll
    for (int i = 0; i < 4; ++i) {
        int idx = tid + i * 256;
        int r = idx >> 3, c = idx & 7;
        uint32_t sw = (uint32_t)(r * 128 + ((c ^ (r & 7)) << 4));
        size_t goff = (qrow0 + r) * DIM + colh + c * 8;
        CP_ASYNC16(sb + FS_Q_OFF + sw, (const char*)(Qh + goff));
    }
    CP_COMMIT();

    auto issue_kv = [&](int kt, int s) {
        const size_t rowbase = (size_t)b * SEQ + (size_t)kt * 64;
        const uint32_t st = sb + s * FS_STAGE;
        #pragma unroll
        for (int i = 0; i < 2; ++i) {
            int idx = tid + i * 256;
            int r = idx >> 3, c = idx & 7;
            uint32_t sw = (uint32_t)(r * 128 + ((c ^ (r & 7)) << 4));
            size_t goff = (rowbase + r) * DIM + colh + c * 8;
            CP_ASYNC16(st + sw,        (const char*)(Kh + goff));
            CP_ASYNC16(st + 8192 + sw, (const char*)(Vh + goff));
        }
        CP_COMMIT();
    };

    // prologue: 2 kv stages in flight
    issue_kv(0, 0);
    issue_kv(1, 1);
    CP_WAIT(1);                      // Q + kv0 complete; kv1 may be pending
    __syncthreads();

    uint32_t qhf[4][4];
    #pragma unroll
    for (int kc = 0; kc < 4; ++kc) {
        int row = wid * 16 + lrow8;
        int col = kc * 32 + lcol16;
        uint32_t ad = sb + FS_Q_OFF + row * 128 + ((((col >> 4) ^ (row & 7)) & 7) << 4);
        LDSM_X4(qhf[kc][0], qhf[kc][1], qhf[kc][2], qhf[kc][3], ad);
    }

    float o[8][4];
    #pragma unroll
    for (int i = 0; i < 8; ++i)
        #pragma unroll
        for (int q = 0; q < 4; ++q) o[i][q] = 0.f;
    float m0 = -1e30f, m1 = -1e30f, l0 = 0.f, l1 = 0.f;   // l: per-thread partials

    int stg = 0;
    for (int kt = 0; kt < FS_NT; ++kt) {
        if (kt) {
            if (kt >= FS_NT - 2) CP_WAIT(0);
            else                 CP_WAIT(1);
            __syncthreads();
        }
        if (kt + 2 < FS_NT) {
            int s2 = stg + 2;
            if (s2 >= FS_NSTG) s2 -= FS_NSTG;
            issue_kv(kt + 2, s2);
        }

        const uint32_t kb = sb + stg * FS_STAGE;
        const uint32_t vb = kb + 8192;
        if (++stg == FS_NSTG) stg = 0;

        float s[8][4];
        #pragma unroll
        for (int i = 0; i < 8; ++i)
            #pragma unroll
            for (int q = 0; q < 4; ++q) s[i][q] = 0.f;

        // S = Q K^T : single pass (Qh*Kh)
        #pragma unroll
        for (int kc = 0; kc < 4; ++kc) {
            const int col = kc * 32 + lcol16;
            #pragma unroll
            for (int nb2 = 0; nb2 < 4; ++nb2) {
                int row = nb2 * 16 + lrow8;
                uint32_t ad = kb + row * 128 + ((((col >> 4) ^ (row & 7)) & 7) << 4);
                uint32_t f0, f1, f2, f3;
                LDSM_X4(f0, f1, f2, f3, ad);
                MMA16816(s[2 * nb2],     qhf[kc], f0, f2);
                MMA16816(s[2 * nb2 + 1], qhf[kc], f1, f3);
            }
        }

        float mx0 = -1e30f, mx1 = -1e30f;
        #pragma unroll
        for (int nb = 0; nb < 8; ++nb) {
            mx0 = fmaxf(mx0, fmaxf(s[nb][0], s[nb][1]));
            mx1 = fmaxf(mx1, fmaxf(s[nb][2], s[nb][3]));
        }
        mx0 = fmaxf(mx0, __shfl_xor_sync(0xffffffffu, mx0, 1));
        mx0 = fmaxf(mx0, __shfl_xor_sync(0xffffffffu, mx0, 2));
        mx1 = fmaxf(mx1, __shfl_xor_sync(0xffffffffu, mx1, 1));
        mx1 = fmaxf(mx1, __shfl_xor_sync(0xffffffffu, mx1, 2));
        float mn0 = fmaxf(m0, mx0), mn1 = fmaxf(m1, mx1);
        float cr0 = ex2f(m0 - mn0), cr1 = ex2f(m1 - mn1);
        m0 = mn0; m1 = mn1;

        float ls0 = 0.f, ls1 = 0.f;
        uint32_t a[4][4];
        #pragma unroll
        for (int nb = 0; nb < 8; ++nb) {
            float p0 = ex2f(s[nb][0] - mn0);
            float p1 = ex2f(s[nb][1] - mn0);
            float p2 = ex2f(s[nb][2] - mn1);
            float p3 = ex2f(s[nb][3] - mn1);
            ls0 += p0 + p1;
            ls1 += p2 + p3;
            __half2 h01 = __floats2half2_rn(p0, p1);
            __half2 h23 = __floats2half2_rn(p2, p3);
            int kc = nb >> 1;
            if ((nb & 1) == 0) {
                a[kc][0] = *(uint32_t*)&h01;
                a[kc][1] = *(uint32_t*)&h23;
            } else {
                a[kc][2] = *(uint32_t*)&h01;
                a[kc][3] = *(uint32_t*)&h23;
            }
        }
        // per-thread l partials (corr uniform across lane quad -> exact)
        l0 = l0 * cr0 + ls0;
        l1 = l1 * cr1 + ls1;
        #pragma unroll
        for (int db = 0; db < 8; ++db) {
            o[db][0] *= cr0; o[db][1] *= cr0;
            o[db][2] *= cr1; o[db][3] *= cr1;
        }

        // O += P V (single pass, fp16 V)
        #pragma unroll
        for (int kc = 0; kc < 4; ++kc) {
            int row = kc * 16 + lrow8;
            #pragma unroll
            for (int db2 = 0; db2 < 4; ++db2) {
                int col = db2 * 32 + lcol16;
                uint32_t ad = vb + row * 128 + ((((col >> 4) ^ (row & 7)) & 7) << 4);
                uint32_t f0, f1, f2, f3;
                LDSM_X4_T(f0, f1, f2, f3, ad);
                MMA16816(o[2 * db2],     a[kc], f0, f1);
                MMA16816(o[2 * db2 + 1], a[kc], f2, f3);
            }
        }
    }

    // deferred cross-lane l reduction
    l0 += __shfl_xor_sync(0xffffffffu, l0, 1);
    l0 += __shfl_xor_sync(0xffffffffu, l0, 2);
    l1 += __shfl_xor_sync(0xffffffffu, l1, 1);
    l1 += __shfl_xor_sync(0xffffffffu, l1, 2);

    float inv0 = 1.0f / l0, inv1 = 1.0f / l1;
    size_t r0 = qrow0 + wid * 16 + (lane >> 2);
    size_t r1 = r0 + 8;
    int cb = colh + (lane & 3) * 2;
    #pragma unroll
    for (int db = 0; db < 8; ++db) {
        __half2 w0 = __floats2half2_rn(o[db][0] * inv0, o[db][1] * inv0);
        __half2 w1 = __floats2half2_rn(o[db][2] * inv1, o[db][3] * inv1);
        *(__half2*)&Ao[r0 * DIM + cb + db * 8] = w0;
        *(__half2*)&Ao[r1 * DIM + cb + db * 8] = w1;
    }
}

// ---------------- launch ----------------
extern "C" void kernel_launch(void* const* d_in, const int* in_sizes, int n_in,
                              void* d_out, int out_size) {
    const float* x      = (const float*)d_in[0];
    const float* y      = (const float*)d_in[1];
    const int*   pos_q  = (const int*)d_in[2];
    const int*   pos_kv = (const int*)d_in[3];
    const float* Wq = (const float*)d_in[4];
    const float* bq = (const float*)d_in[5];
    const float* Wk = (const float*)d_in[6];
    const float* bk = (const float*)d_in[7];
    const float* Wv = (const float*)d_in[8];
    const float* bv = (const float*)d_in[9];
    const float* Wo = (const float*)d_in[10];
    const float* bo = (const float*)d_in[11];
    float* out = (float*)d_out;

    __half *Xh, *Yh, *WTq, *WTk, *WTv, *WTo;
    __half *Qhp, *Khp, *Vhp, *Aohp;
    cudaGetSymbolAddress((void**)&Xh, g_Xh);
    cudaGetSymbolAddress((void**)&Yh, g_Yh);
    cudaGetSymbolAddress((void**)&WTq, g_WTq);
    cudaGetSymbolAddress((void**)&WTk, g_WTk);
    cudaGetSymbolAddress((void**)&WTv, g_WTv);
    cudaGetSymbolAddress((void**)&WTo, g_WTo);
    cudaGetSymbolAddress((void**)&Qhp, g_Qh);
    cudaGetSymbolAddress((void**)&Khp, g_Kh);
    cudaGetSymbolAddress((void**)&Vhp, g_Vh);
    cudaGetSymbolAddress((void**)&Aohp, g_Aoh);

    cudaFuncSetAttribute(qkv_gemm_kernel, cudaFuncAttributeMaxDynamicSharedMemorySize, GEMM_SMEM);
    cudaFuncSetAttribute(out_gemm_kernel, cudaFuncAttributeMaxDynamicSharedMemorySize, GEMM_SMEM);
    cudaFuncSetAttribute(flash16_kernel, cudaFuncAttributeMaxDynamicSharedMemorySize, FS_SMEM);

    const int n4 = (ROWS * DIM) / 4;
    f2h2_kernel<<<dim3((n4 + 255) / 256, 2), 256>>>(x, y, Xh, Yh, n4);

    transpose4_kernel<<<dim3(DIM / 32, DIM / 32, 4), dim3(32, 8)>>>(
        Wq, Wk, Wv, Wo, WTq, WTk, WTv, WTo);

    qkv_gemm_kernel<<<dim3(DIM / 128, ROWS / 128, 3), 256, GEMM_SMEM>>>(
        Xh, Yh, WTq, WTk, WTv, bq, bk, bv, pos_q, pos_kv,
        Qhp, Khp, Vhp);

    flash16_kernel<<<dim3(SEQ / 128, HEADS, BATCH), 256, FS_SMEM>>>(
        Qhp, Khp, Vhp, Aohp);

    out_gemm_kernel<<<dim3(DIM / 128, ROWS / 128), 256, GEMM_SMEM>>>(Aohp, WTo, bo, out);
}

// round 16
// speedup vs baseline: 1.0559x; 1.0252x over previous
#include <cuda_runtime.h>
#include <cuda_fp16.h>
#include <math.h>
#include <stdint.h>

#define HEADS 12
#define DH 64
#define DIM 768
#define BATCH 8
#define SEQ 1024
#define ROWS (BATCH * SEQ)   // 8192

#define QSCALE 0.1803368801111204f   // 0.125 * log2(e)

// ---------------- scratch ----------------
__device__ __half g_Xh[ROWS * DIM];
__device__ __half g_Yh[ROWS * DIM];
__device__ __half g_WTq[DIM * DIM];
__device__ __half g_WTk[DIM * DIM];
__device__ __half g_WTv[DIM * DIM];
__device__ __half g_WTo[DIM * DIM];
__device__ __half g_Qh[ROWS * DIM];
__device__ __half g_Kh[ROWS * DIM];
__device__ __half g_Vh[ROWS * DIM];
__device__ __half g_Aoh[ROWS * DIM];
__device__ float g_cosT[512];
__device__ float g_sinT[512];

// ---------------- helpers ----------------
__device__ __forceinline__ uint32_t smem_u32(const void* p) {
    uint32_t a;
    asm("{ .reg .u64 t; cvta.to.shared.u64 t, %1; cvt.u32.u64 %0, t; }" : "=r"(a) : "l"(p));
    return a;
}
__device__ __forceinline__ float ex2f(float x) {
    float y;
    asm("ex2.approx.ftz.f32 %0, %1;" : "=f"(y) : "f"(x));
    return y;
}

#define LDSM_X4(r0, r1, r2, r3, addr)                                          \
    asm volatile("ldmatrix.sync.aligned.m8n8.x4.shared.b16 {%0,%1,%2,%3}, [%4];" \
                 : "=r"(r0), "=r"(r1), "=r"(r2), "=r"(r3) : "r"(addr))

#define LDSM_X4_T(r0, r1, r2, r3, addr)                                        \
    asm volatile("ldmatrix.sync.aligned.m8n8.x4.trans.shared.b16 {%0,%1,%2,%3}, [%4];" \
                 : "=r"(r0), "=r"(r1), "=r"(r2), "=r"(r3) : "r"(addr))

#define MMA16816(c, a, b0, b1)                                                 \
    asm volatile("mma.sync.aligned.m16n8k16.row.col.f32.f16.f16.f32 "          \
                 "{%0,%1,%2,%3}, {%4,%5,%6,%7}, {%8,%9}, {%0,%1,%2,%3};"       \
                 : "+f"((c)[0]), "+f"((c)[1]), "+f"((c)[2]), "+f"((c)[3])      \
                 : "r"((a)[0]), "r"((a)[1]), "r"((a)[2]), "r"((a)[3]),         \
                   "r"(b0), "r"(b1))

#define CP_ASYNC16(dst, src)                                                   \
    asm volatile("cp.async.cg.shared.global [%0], [%1], 16;" :: "r"(dst), "l"(src))
#define CP_COMMIT() asm volatile("cp.async.commit_group;" ::: "memory")
#define CP_WAIT(n)  asm volatile("cp.async.wait_group %0;" :: "n"(n) : "memory")

// ---------------- float -> half (x and y in one launch) ----------------
__global__ void f2h2_kernel(const float* __restrict__ x, const float* __restrict__ y,
                            __half* __restrict__ Xh, __half* __restrict__ Yh, int n4) {
    int i = blockIdx.x * blockDim.x + threadIdx.x;
    if (i >= n4) return;
    const float* src = blockIdx.y ? y : x;
    __half* dst = blockIdx.y ? Yh : Xh;
    float4 v = ((const float4*)src)[i];
    __half2 lo = __floats2half2_rn(v.x, v.y);
    __half2 hi = __floats2half2_rn(v.z, v.w);
    uint2 o;
    o.x = *(uint32_t*)&lo;
    o.y = *(uint32_t*)&hi;
    ((uint2*)dst)[i] = o;
}

// ---------------- 4 weight transposes + RoPE table init in one launch ----------------
__global__ void transpose4_kernel(const float* __restrict__ Wq, const float* __restrict__ Wk,
                                  const float* __restrict__ Wv, const float* __restrict__ Wo,
                                  __half* __restrict__ Tq, __half* __restrict__ Tk,
                                  __half* __restrict__ Tv, __half* __restrict__ To) {
    const int z = blockIdx.z;
    if (z == 0 && blockIdx.x == 0 && blockIdx.y == 0) {
        int t = threadIdx.y * 32 + threadIdx.x;
        #pragma unroll
        for (int rep = 0; rep < 2; ++rep) {
            int i = t + rep * 256;
            int p = i >> 4;
            int f = i & 15;
            double inv = pow(100.0, -((double)(2 * f)) / 32.0);
            double fr = (double)p * inv;
            g_cosT[i] = (float)cos(fr);
            g_sinT[i] = (float)sin(fr);
        }
    }
    const float* W = (z == 0) ? Wq : (z == 1) ? Wk : (z == 2) ? Wv : Wo;
    __half* T = (z == 0) ? Tq : (z == 1) ? Tk : (z == 2) ? Tv : To;
    __shared__ float tile[32][33];
    int bx = blockIdx.x * 32;
    int by = blockIdx.y * 32;
    int x = threadIdx.x, y = threadIdx.y;
    #pragma unroll
    for (int j = 0; j < 4; ++j)
        tile[y + 8 * j][x] = W[(by + y + 8 * j) * DIM + bx + x];
    __syncthreads();
    #pragma unroll
    for (int j = 0; j < 4; ++j)
        T[(size_t)(bx + y + 8 * j) * DIM + by + x] = __float2half(tile[x][y + 8 * j]);
}

// ---------------- GEMM tile constants (3-stage pipeline) ----------------
#define NKT (DIM / 64)
#define AS_BYTES (128 * 128)
#define STAGE_B (2 * AS_BYTES)
#define GEMM_NSTG 3
#define GEMM_SMEM (GEMM_NSTG * STAGE_B)   // 98304

// ---------------- fused Q/K/V projection GEMM (one launch, z picks mode) ----------------
__global__ __launch_bounds__(256, 2) void qkv_gemm_kernel(
    const __half* __restrict__ Xh, const __half* __restrict__ Yh,
    const __half* __restrict__ WTq, const __half* __restrict__ WTk, const __half* __restrict__ WTv,
    const float* __restrict__ bq, const float* __restrict__ bk, const float* __restrict__ bv,
    const int* __restrict__ pos_q, const int* __restrict__ pos_kv,
    __half* __restrict__ Qh, __half* __restrict__ Kh, __half* __restrict__ Vh)
{
    extern __shared__ char sm[];
    const uint32_t sbase = smem_u32(sm);
    const int z = blockIdx.z;
    const __half* A = (z == 0) ? Xh : Yh;
    const __half* B = (z == 0) ? WTq : (z == 1) ? WTk : WTv;
    const float* bias = (z == 0) ? bq : (z == 1) ? bk : bv;
    const int* pos = (z == 0) ? pos_q : pos_kv;
    __half* Ch = (z == 0) ? Qh : (z == 1) ? Kh : Vh;

    const int tid  = threadIdx.x;
    const int lane = tid & 31;
    const int wid  = tid >> 5;
    const int warpM = wid & 3;
    const int warpN = wid >> 2;
    const int m0 = blockIdx.y * 128;
    const int n0 = blockIdx.x * 128;

    float c[2][8][4];
    #pragma unroll
    for (int i = 0; i < 2; ++i)
        #pragma unroll
        for (int j = 0; j < 8; ++j)
            #pragma unroll
            for (int q = 0; q < 4; ++q) c[i][j][q] = 0.f;

    const int rr0 = tid >> 3;
    const int cc  = tid & 7;

    auto issue_stage = [&](int kt, int s) {
        #pragma unroll
        for (int i = 0; i < 4; ++i) {
            int r = rr0 + i * 32;
            uint32_t sw = (uint32_t)(r * 128 + ((cc ^ (r & 7)) << 4));
            uint32_t da = sbase + s * STAGE_B + sw;
            uint32_t db = da + AS_BYTES;
            const char* ga = (const char*)(A + (size_t)(m0 + r) * DIM + kt * 64 + cc * 8);
            const char* gb = (const char*)(B + (size_t)(n0 + r) * DIM + kt * 64 + cc * 8);
            CP_ASYNC16(da, ga);
            CP_ASYNC16(db, gb);
        }
        CP_COMMIT();
    };

    const int lrow8 = ((lane >> 3) & 1) * 8 + (lane & 7);
    const int lcol16 = (lane >> 4) * 16;

    issue_stage(0, 0);
    issue_stage(1, 1);

    int stg = 0;
    for (int kt = 0; kt < NKT; ++kt) {
        if (kt == NKT - 1) CP_WAIT(0);
        else               CP_WAIT(1);
        __syncthreads();
        if (kt + 2 < NKT) {
            int s2 = stg + 2;
            if (s2 >= GEMM_NSTG) s2 -= GEMM_NSTG;
            issue_stage(kt + 2, s2);
        }

        const uint32_t ab = sbase + stg * STAGE_B;
        const uint32_t bb = ab + AS_BYTES;
        if (++stg == GEMM_NSTG) stg = 0;

        #pragma unroll
        for (int ks = 0; ks < 4; ++ks) {
            const int kb = ks * 32;
            uint32_t af[2][4];
            #pragma unroll
            for (int i = 0; i < 2; ++i) {
                int row = warpM * 32 + i * 16 + lrow8;
                int col = kb + lcol16;
                uint32_t ad = ab + row * 128 + ((((col >> 4) ^ (row & 7)) & 7) << 4);
                LDSM_X4(af[i][0], af[i][1], af[i][2], af[i][3], ad);
            }
            uint32_t bf[4][4];
            #pragma unroll
            for (int jj = 0; jj < 4; ++jj) {
                int nrow = warpN * 64 + jj * 16 + lrow8;
                int col = kb + lcol16;
                uint32_t bd = bb + nrow * 128 + ((((col >> 4) ^ (nrow & 7)) & 7) << 4);
                LDSM_X4(bf[jj][0], bf[jj][1], bf[jj][2], bf[jj][3], bd);
            }
            #pragma unroll
            for (int i = 0; i < 2; ++i) {
                #pragma unroll
                for (int j = 0; j < 8; ++j) {
                    const int jj = j >> 1, sel = j & 1;
                    MMA16816(c[i][j], af[i], bf[jj][sel], bf[jj][sel + 2]);
                }
            }
        }
    }

    // ---------------- fused epilogue ----------------
    if (z == 2) {
        #pragma unroll
        for (int i = 0; i < 2; ++i) {
            #pragma unroll
            for (int j = 0; j < 8; ++j) {
                int row = m0 + warpM * 32 + i * 16 + (lane >> 2);
                int col = n0 + warpN * 64 + j * 8 + (lane & 3) * 2;
                float b0v = bias[col], b1v = bias[col + 1];
                *(__half2*)&Ch[(size_t)row * DIM + col] =
                    __floats2half2_rn(c[i][j][0] + b0v, c[i][j][1] + b1v);
                *(__half2*)&Ch[(size_t)(row + 8) * DIM + col] =
                    __floats2half2_rn(c[i][j][2] + b0v, c[i][j][3] + b1v);
            }
        }
    } else {
        const float scale = (z == 0) ? QSCALE : 1.0f;
        #pragma unroll
        for (int i = 0; i < 2; ++i) {
            int rowA = m0 + warpM * 32 + i * 16 + (lane >> 2);
            int rowB = rowA + 8;
            int pA0 = pos[2 * rowA], pA1 = pos[2 * rowA + 1];
            int pB0 = pos[2 * rowB], pB1 = pos[2 * rowB + 1];
            #pragma unroll
            for (int jj = 0; jj < 4; ++jj) {
                const int j = (jj < 2) ? jj : jj + 2;   // 0,1,4,5
                const int half = (j >= 4);
                int col = n0 + warpN * 64 + j * 8 + (lane & 3) * 2;
                int f0 = (j & 1) * 8 + (lane & 3) * 2;
                int pA = half ? pA1 : pA0;
                int pB = half ? pB1 : pB0;
                float cA0 = g_cosT[pA * 16 + f0], cA1 = g_cosT[pA * 16 + f0 + 1];
                float sA0 = g_sinT[pA * 16 + f0], sA1 = g_sinT[pA * 16 + f0 + 1];
                float cB0 = g_cosT[pB * 16 + f0], cB1 = g_cosT[pB * 16 + f0 + 1];
                float sB0 = g_sinT[pB * 16 + f0], sB1 = g_sinT[pB * 16 + f0 + 1];
                float b1x = bias[col], b1y = bias[col + 1];
                float b2x = bias[col + 16], b2y = bias[col + 17];

                {
                    float v1x = c[i][j][0] + b1x,     v1y = c[i][j][1] + b1y;
                    float v2x = c[i][j + 2][0] + b2x, v2y = c[i][j + 2][1] + b2y;
                    *(__half2*)&Ch[(size_t)rowA * DIM + col] =
                        __floats2half2_rn((v1x * cA0 - v2x * sA0) * scale,
                                          (v1y * cA1 - v2y * sA1) * scale);
                    *(__half2*)&Ch[(size_t)rowA * DIM + col + 16] =
                        __floats2half2_rn((v2x * cA0 + v1x * sA0) * scale,
                                          (v2y * cA1 + v1y * sA1) * scale);
                }
                {
                    float v1x = c[i][j][2] + b1x,     v1y = c[i][j][3] + b1y;
                    float v2x = c[i][j + 2][2] + b2x, v2y = c[i][j + 2][3] + b2y;
                    *(__half2*)&Ch[(size_t)rowB * DIM + col] =
                        __floats2half2_rn((v1x * cB0 - v2x * sB0) * scale,
                                          (v1y * cB1 - v2y * sB1) * scale);
                    *(__half2*)&Ch[(size_t)rowB * DIM + col + 16] =
                        __floats2half2_rn((v2x * cB0 + v1x * sB0) * scale,
                                          (v2y * cB1 + v1y * sB1) * scale);
                }
            }
        }
    }
}

// ---------------- final output GEMM: out = Aoh @ WTo^T + bo (fp32) ----------------
__global__ __launch_bounds__(256, 2) void out_gemm_kernel(
    const __half* __restrict__ A, const __half* __restrict__ B,
    const float* __restrict__ bias, float* __restrict__ Cf)
{
    extern __shared__ char sm[];
    const uint32_t sbase = smem_u32(sm);
    const int tid  = threadIdx.x;
    const int lane = tid & 31;
    const int wid  = tid >> 5;
    const int warpM = wid & 3;
    const int warpN = wid >> 2;
    const int m0 = blockIdx.y * 128;
    const int n0 = blockIdx.x * 128;

    float c[2][8][4];
    #pragma unroll
    for (int i = 0; i < 2; ++i)
        #pragma unroll
        for (int j = 0; j < 8; ++j)
            #pragma unroll
            for (int q = 0; q < 4; ++q) c[i][j][q] = 0.f;

    const int rr0 = tid >> 3;
    const int cc  = tid & 7;

    auto issue_stage = [&](int kt, int s) {
        #pragma unroll
        for (int i = 0; i < 4; ++i) {
            int r = rr0 + i * 32;
            uint32_t sw = (uint32_t)(r * 128 + ((cc ^ (r & 7)) << 4));
            uint32_t da = sbase + s * STAGE_B + sw;
            uint32_t db = da + AS_BYTES;
            const char* ga = (const char*)(A + (size_t)(m0 + r) * DIM + kt * 64 + cc * 8);
            const char* gb = (const char*)(B + (size_t)(n0 + r) * DIM + kt * 64 + cc * 8);
            CP_ASYNC16(da, ga);
            CP_ASYNC16(db, gb);
        }
        CP_COMMIT();
    };

    const int lrow8 = ((lane >> 3) & 1) * 8 + (lane & 7);
    const int lcol16 = (lane >> 4) * 16;

    issue_stage(0, 0);
    issue_stage(1, 1);

    int stg = 0;
    for (int kt = 0; kt < NKT; ++kt) {
        if (kt == NKT - 1) CP_WAIT(0);
        else               CP_WAIT(1);
        __syncthreads();
        if (kt + 2 < NKT) {
            int s2 = stg + 2;
            if (s2 >= GEMM_NSTG) s2 -= GEMM_NSTG;
            issue_stage(kt + 2, s2);
        }

        const uint32_t ab = sbase + stg * STAGE_B;
        const uint32_t bb = ab + AS_BYTES;
        if (++stg == GEMM_NSTG) stg = 0;

        #pragma unroll
        for (int ks = 0; ks < 4; ++ks) {
            const int kb = ks * 32;
            uint32_t af[2][4];
            #pragma unroll
            for (int i = 0; i < 2; ++i) {
                int row = warpM * 32 + i * 16 + lrow8;
                int col = kb + lcol16;
                uint32_t ad = ab + row * 128 + ((((col >> 4) ^ (row & 7)) & 7) << 4);
                LDSM_X4(af[i][0], af[i][1], af[i][2], af[i][3], ad);
            }
            uint32_t bf[4][4];
            #pragma unroll
            for (int jj = 0; jj < 4; ++jj) {
                int nrow = warpN * 64 + jj * 16 + lrow8;
                int col = kb + lcol16;
                uint32_t bd = bb + nrow * 128 + ((((col >> 4) ^ (nrow & 7)) & 7) << 4);
                LDSM_X4(bf[jj][0], bf[jj][1], bf[jj][2], bf[jj][3], bd);
            }
            #pragma unroll
            for (int i = 0; i < 2; ++i) {
                #pragma unroll
                for (int j = 0; j < 8; ++j) {
                    const int jj = j >> 1, sel = j & 1;
                    MMA16816(c[i][j], af[i], bf[jj][sel], bf[jj][sel + 2]);
                }
            }
        }
    }

    #pragma unroll
    for (int i = 0; i < 2; ++i) {
        #pragma unroll
        for (int j = 0; j < 8; ++j) {
            int row = m0 + warpM * 32 + i * 16 + (lane >> 2);
            int col = n0 + warpN * 64 + j * 8 + (lane & 3) * 2;
            float b0v = bias[col], b1v = bias[col + 1];
            float2 o0 = {c[i][j][0] + b0v, c[i][j][1] + b1v};
            float2 o1 = {c[i][j][2] + b0v, c[i][j][3] + b1v};
            *(float2*)&Cf[(size_t)row * DIM + col] = o0;
            *(float2*)&Cf[(size_t)(row + 8) * DIM + col] = o1;
        }
    }
}

// ---------------- fp16 flash attention: 64q x 64kv CTAs (4 warps), 3-stage pipeline ----------------
#define FS_STAGE 16384
#define FS_NSTG 3
#define FS_Q_OFF (FS_NSTG * FS_STAGE)           // 49152
#define FS_SMEM (FS_Q_OFF + 8192)               // 57344
#define FS_NT (SEQ / 64)                        // 16

__global__ __launch_bounds__(128, 4) void flash16_kernel(
    const __half* __restrict__ Qh, const __half* __restrict__ Kh,
    const __half* __restrict__ Vh, __half* __restrict__ Ao)
{
    extern __shared__ char sm[];
    const uint32_t sb = smem_u32(sm);
    const int tid  = threadIdx.x;
    const int lane = tid & 31;
    const int wid  = tid >> 5;       // 0..3
    const int qb   = blockIdx.x * 64;
    const int h    = blockIdx.y;
    const int b    = blockIdx.z;
    const size_t qrow0 = (size_t)b * SEQ + qb;
    const int colh = h * DH;

    const int lrow8  = ((lane >> 3) & 1) * 8 + (lane & 7);
    const int lcol16 = (lane >> 4) * 16;

    // Q tile load (64 x 64 halves = 8 KB), its own cp.async group
    #pragma unroll
    for (int i = 0; i < 4; ++i) {
        int idx = tid + i * 128;          // 0..511
        int r = idx >> 3, c = idx & 7;    // r: 0..63
        uint32_t sw = (uint32_t)(r * 128 + ((c ^ (r & 7)) << 4));
        size_t goff = (qrow0 + r) * DIM + colh + c * 8;
        CP_ASYNC16(sb + FS_Q_OFF + sw, (const char*)(Qh + goff));
    }
    CP_COMMIT();

    auto issue_kv = [&](int kt, int s) {
        const size_t rowbase = (size_t)b * SEQ + (size_t)kt * 64;
        const uint32_t st = sb + s * FS_STAGE;
        #pragma unroll
        for (int i = 0; i < 4; ++i) {
            int idx = tid + i * 128;      // 0..511
            int r = idx >> 3, c = idx & 7;
            uint32_t sw = (uint32_t)(r * 128 + ((c ^ (r & 7)) << 4));
            size_t goff = (rowbase + r) * DIM + colh + c * 8;
            CP_ASYNC16(st + sw,        (const char*)(Kh + goff));
            CP_ASYNC16(st + 8192 + sw, (const char*)(Vh + goff));
        }
        CP_COMMIT();
    };

    // prologue: 2 kv stages in flight
    issue_kv(0, 0);
    issue_kv(1, 1);
    CP_WAIT(1);                      // Q + kv0 complete; kv1 may be pending
    __syncthreads();

    uint32_t qhf[4][4];
    #pragma unroll
    for (int kc = 0; kc < 4; ++kc) {
        int row = wid * 16 + lrow8;
        int col = kc * 32 + lcol16;
        uint32_t ad = sb + FS_Q_OFF + row * 128 + ((((col >> 4) ^ (row & 7)) & 7) << 4);
        LDSM_X4(qhf[kc][0], qhf[kc][1], qhf[kc][2], qhf[kc][3], ad);
    }

    float o[8][4];
    #pragma unroll
    for (int i = 0; i < 8; ++i)
        #pragma unroll
        for (int q = 0; q < 4; ++q) o[i][q] = 0.f;
    float m0 = -1e30f, m1 = -1e30f, l0 = 0.f, l1 = 0.f;   // l: per-thread partials

    int stg = 0;
    for (int kt = 0; kt < FS_NT; ++kt) {
        if (kt) {
            if (kt >= FS_NT - 2) CP_WAIT(0);
            else                 CP_WAIT(1);
            __syncthreads();
        }
        if (kt + 2 < FS_NT) {
            int s2 = stg + 2;
            if (s2 >= FS_NSTG) s2 -= FS_NSTG;
            issue_kv(kt + 2, s2);
        }

        const uint32_t kb = sb + stg * FS_STAGE;
        const uint32_t vb = kb + 8192;
        if (++stg == FS_NSTG) stg = 0;

        float s[8][4];
        #pragma unroll
        for (int i = 0; i < 8; ++i)
            #pragma unroll
            for (int q = 0; q < 4; ++q) s[i][q] = 0.f;

        // S = Q K^T : single pass (Qh*Kh)
        #pragma unroll
        for (int kc = 0; kc < 4; ++kc) {
            const int col = kc * 32 + lcol16;
            #pragma unroll
            for (int nb2 = 0; nb2 < 4; ++nb2) {
                int row = nb2 * 16 + lrow8;
                uint32_t ad = kb + row * 128 + ((((col >> 4) ^ (row & 7)) & 7) << 4);
                uint32_t f0, f1, f2, f3;
                LDSM_X4(f0, f1, f2, f3, ad);
                MMA16816(s[2 * nb2],     qhf[kc], f0, f2);
                MMA16816(s[2 * nb2 + 1], qhf[kc], f1, f3);
            }
        }

        float mx0 = -1e30f, mx1 = -1e30f;
        #pragma unroll
        for (int nb = 0; nb < 8; ++nb) {
            mx0 = fmaxf(mx0, fmaxf(s[nb][0], s[nb][1]));
            mx1 = fmaxf(mx1, fmaxf(s[nb][2], s[nb][3]));
        }
        mx0 = fmaxf(mx0, __shfl_xor_sync(0xffffffffu, mx0, 1));
        mx0 = fmaxf(mx0, __shfl_xor_sync(0xffffffffu, mx0, 2));
        mx1 = fmaxf(mx1, __shfl_xor_sync(0xffffffffu, mx1, 1));
        mx1 = fmaxf(mx1, __shfl_xor_sync(0xffffffffu, mx1, 2));
        float mn0 = fmaxf(m0, mx0), mn1 = fmaxf(m1, mx1);
        float cr0 = ex2f(m0 - mn0), cr1 = ex2f(m1 - mn1);
        m0 = mn0; m1 = mn1;

        float ls0 = 0.f, ls1 = 0.f;
        uint32_t a[4][4];
        #pragma unroll
        for (int nb = 0; nb < 8; ++nb) {
            float p0 = ex2f(s[nb][0] - mn0);
            float p1 = ex2f(s[nb][1] - mn0);
            float p2 = ex2f(s[nb][2] - mn1);
            float p3 = ex2f(s[nb][3] - mn1);
            ls0 += p0 + p1;
            ls1 += p2 + p3;
            __half2 h01 = __floats2half2_rn(p0, p1);
            __half2 h23 = __floats2half2_rn(p2, p3);
            int kc = nb >> 1;
            if ((nb & 1) == 0) {
                a[kc][0] = *(uint32_t*)&h01;
                a[kc][1] = *(uint32_t*)&h23;
            } else {
                a[kc][2] = *(uint32_t*)&h01;
                a[kc][3] = *(uint32_t*)&h23;
            }
        }
        // per-thread l partials (corr uniform across lane quad -> exact)
        l0 = l0 * cr0 + ls0;
        l1 = l1 * cr1 + ls1;
        #pragma unroll
        for (int db = 0; db < 8; ++db) {
            o[db][0] *= cr0; o[db][1] *= cr0;
            o[db][2] *= cr1; o[db][3] *= cr1;
        }

        // O += P V (single pass, fp16 V)
        #pragma unroll
        for (int kc = 0; kc < 4; ++kc) {
            int row = kc * 16 + lrow8;
            #pragma unroll
            for (int db2 = 0; db2 < 4; ++db2) {
                int col = db2 * 32 + lcol16;
                uint32_t ad = vb + row * 128 + ((((col >> 4) ^ (row & 7)) & 7) << 4);
                uint32_t f0, f1, f2, f3;
                LDSM_X4_T(f0, f1, f2, f3, ad);
                MMA16816(o[2 * db2],     a[kc], f0, f1);
                MMA16816(o[2 * db2 + 1], a[kc], f2, f3);
            }
        }
    }

    // deferred cross-lane l reduction
    l0 += __shfl_xor_sync(0xffffffffu, l0, 1);
    l0 += __shfl_xor_sync(0xffffffffu, l0, 2);
    l1 += __shfl_xor_sync(0xffffffffu, l1, 1);
    l1 += __shfl_xor_sync(0xffffffffu, l1, 2);

    float inv0 = 1.0f / l0, inv1 = 1.0f / l1;
    size_t r0 = qrow0 + wid * 16 + (lane >> 2);
    size_t r1 = r0 + 8;
    int cb = colh + (lane & 3) * 2;
    #pragma unroll
    for (int db = 0; db < 8; ++db) {
        __half2 w0 = __floats2half2_rn(o[db][0] * inv0, o[db][1] * inv0);
        __half2 w1 = __floats2half2_rn(o[db][2] * inv1, o[db][3] * inv1);
        *(__half2*)&Ao[r0 * DIM + cb + db * 8] = w0;
        *(__half2*)&Ao[r1 * DIM + cb + db * 8] = w1;
    }
}

// ---------------- launch ----------------
extern "C" void kernel_launch(void* const* d_in, const int* in_sizes, int n_in,
                              void* d_out, int out_size) {
    const float* x      = (const float*)d_in[0];
    const float* y      = (const float*)d_in[1];
    const int*   pos_q  = (const int*)d_in[2];
    const int*   pos_kv = (const int*)d_in[3];
    const float* Wq = (const float*)d_in[4];
    const float* bq = (const float*)d_in[5];
    const float* Wk = (const float*)d_in[6];
    const float* bk = (const float*)d_in[7];
    const float* Wv = (const float*)d_in[8];
    const float* bv = (const float*)d_in[9];
    const float* Wo = (const float*)d_in[10];
    const float* bo = (const float*)d_in[11];
    float* out = (float*)d_out;

    __half *Xh, *Yh, *WTq, *WTk, *WTv, *WTo;
    __half *Qhp, *Khp, *Vhp, *Aohp;
    cudaGetSymbolAddress((void**)&Xh, g_Xh);
    cudaGetSymbolAddress((void**)&Yh, g_Yh);
    cudaGetSymbolAddress((void**)&WTq, g_WTq);
    cudaGetSymbolAddress((void**)&WTk, g_WTk);
    cudaGetSymbolAddress((void**)&WTv, g_WTv);
    cudaGetSymbolAddress((void**)&WTo, g_WTo);
    cudaGetSymbolAddress((void**)&Qhp, g_Qh);
    cudaGetSymbolAddress((void**)&Khp, g_Kh);
    cudaGetSymbolAddress((void**)&Vhp, g_Vh);
    cudaGetSymbolAddress((void**)&Aohp, g_Aoh);

    cudaFuncSetAttribute(qkv_gemm_kernel, cudaFuncAttributeMaxDynamicSharedMemorySize, GEMM_SMEM);
    cudaFuncSetAttribute(out_gemm_kernel, cudaFuncAttributeMaxDynamicSharedMemorySize, GEMM_SMEM);
    cudaFuncSetAttribute(flash16_kernel, cudaFuncAttributeMaxDynamicSharedMemorySize, FS_SMEM);

    const int n4 = (ROWS * DIM) / 4;
    f2h2_kernel<<<dim3((n4 + 255) / 256, 2), 256>>>(x, y, Xh, Yh, n4);

    transpose4_kernel<<<dim3(DIM / 32, DIM / 32, 4), dim3(32, 8)>>>(
        Wq, Wk, Wv, Wo, WTq, WTk, WTv, WTo);

    qkv_gemm_kernel<<<dim3(DIM / 128, ROWS / 128, 3), 256, GEMM_SMEM>>>(
        Xh, Yh, WTq, WTk, WTv, bq, bk, bv, pos_q, pos_kv,
        Qhp, Khp, Vhp);

    flash16_kernel<<<dim3(SEQ / 64, HEADS, BATCH), 128, FS_SMEM>>>(
        Qhp, Khp, Vhp, Aohp);

    out_gemm_kernel<<<dim3(DIM / 128, ROWS / 128), 256, GEMM_SMEM>>>(Aohp, WTo, bo, out);
}

// round 17
// speedup vs baseline: 1.0749x; 1.0180x over previous
#include <cuda_runtime.h>
#include <cuda_fp16.h>
#include <math.h>
#include <stdint.h>

#define HEADS 12
#define DH 64
#define DIM 768
#define BATCH 8
#define SEQ 1024
#define ROWS (BATCH * SEQ)   // 8192

#define QSCALE 0.1803368801111204f   // 0.125 * log2(e)

// ---------------- scratch ----------------
__device__ __half g_Xh[ROWS * DIM];
__device__ __half g_Yh[ROWS * DIM];
__device__ __half g_WTq[DIM * DIM];
__device__ __half g_WTk[DIM * DIM];
__device__ __half g_WTv[DIM * DIM];
__device__ __half g_WTo[DIM * DIM];
__device__ __half g_Qh[ROWS * DIM];
__device__ __half g_Kh[ROWS * DIM];
__device__ __half g_Vh[ROWS * DIM];
__device__ __half g_Aoh[ROWS * DIM];
__device__ float g_cosT[512];
__device__ float g_sinT[512];

// ---------------- helpers ----------------
__device__ __forceinline__ uint32_t smem_u32(const void* p) {
    uint32_t a;
    asm("{ .reg .u64 t; cvta.to.shared.u64 t, %1; cvt.u32.u64 %0, t; }" : "=r"(a) : "l"(p));
    return a;
}
__device__ __forceinline__ float ex2f(float x) {
    float y;
    asm("ex2.approx.ftz.f32 %0, %1;" : "=f"(y) : "f"(x));
    return y;
}

#define LDSM_X4(r0, r1, r2, r3, addr)                                          \
    asm volatile("ldmatrix.sync.aligned.m8n8.x4.shared.b16 {%0,%1,%2,%3}, [%4];" \
                 : "=r"(r0), "=r"(r1), "=r"(r2), "=r"(r3) : "r"(addr))

#define LDSM_X4_T(r0, r1, r2, r3, addr)                                        \
    asm volatile("ldmatrix.sync.aligned.m8n8.x4.trans.shared.b16 {%0,%1,%2,%3}, [%4];" \
                 : "=r"(r0), "=r"(r1), "=r"(r2), "=r"(r3) : "r"(addr))

#define MMA16816(c, a, b0, b1)                                                 \
    asm volatile("mma.sync.aligned.m16n8k16.row.col.f32.f16.f16.f32 "          \
                 "{%0,%1,%2,%3}, {%4,%5,%6,%7}, {%8,%9}, {%0,%1,%2,%3};"       \
                 : "+f"((c)[0]), "+f"((c)[1]), "+f"((c)[2]), "+f"((c)[3])      \
                 : "r"((a)[0]), "r"((a)[1]), "r"((a)[2]), "r"((a)[3]),         \
                   "r"(b0), "r"(b1))

#define CP_ASYNC16(dst, src)                                                   \
    asm volatile("cp.async.cg.shared.global [%0], [%1], 16;" :: "r"(dst), "l"(src))
#define CP_COMMIT() asm volatile("cp.async.commit_group;" ::: "memory")
#define CP_WAIT(n)  asm volatile("cp.async.wait_group %0;" :: "n"(n) : "memory")

// ---------------- float -> half (x and y in one launch) ----------------
__global__ void f2h2_kernel(const float* __restrict__ x, const float* __restrict__ y,
                            __half* __restrict__ Xh, __half* __restrict__ Yh, int n4) {
    int i = blockIdx.x * blockDim.x + threadIdx.x;
    if (i >= n4) return;
    const float* src = blockIdx.y ? y : x;
    __half* dst = blockIdx.y ? Yh : Xh;
    float4 v = ((const float4*)src)[i];
    __half2 lo = __floats2half2_rn(v.x, v.y);
    __half2 hi = __floats2half2_rn(v.z, v.w);
    uint2 o;
    o.x = *(uint32_t*)&lo;
    o.y = *(uint32_t*)&hi;
    ((uint2*)dst)[i] = o;
}

// ---------------- 4 weight transposes + RoPE table init in one launch ----------------
__global__ void transpose4_kernel(const float* __restrict__ Wq, const float* __restrict__ Wk,
                                  const float* __restrict__ Wv, const float* __restrict__ Wo,
                                  __half* __restrict__ Tq, __half* __restrict__ Tk,
                                  __half* __restrict__ Tv, __half* __restrict__ To) {
    const int z = blockIdx.z;
    if (z == 0 && blockIdx.x == 0 && blockIdx.y == 0) {
        int t = threadIdx.y * 32 + threadIdx.x;
        #pragma unroll
        for (int rep = 0; rep < 2; ++rep) {
            int i = t + rep * 256;
            int p = i >> 4;
            int f = i & 15;
            double inv = pow(100.0, -((double)(2 * f)) / 32.0);
            double fr = (double)p * inv;
            g_cosT[i] = (float)cos(fr);
            g_sinT[i] = (float)sin(fr);
        }
    }
    const float* W = (z == 0) ? Wq : (z == 1) ? Wk : (z == 2) ? Wv : Wo;
    __half* T = (z == 0) ? Tq : (z == 1) ? Tk : (z == 2) ? Tv : To;
    __shared__ float tile[32][33];
    int bx = blockIdx.x * 32;
    int by = blockIdx.y * 32;
    int x = threadIdx.x, y = threadIdx.y;
    #pragma unroll
    for (int j = 0; j < 4; ++j)
        tile[y + 8 * j][x] = W[(by + y + 8 * j) * DIM + bx + x];
    __syncthreads();
    #pragma unroll
    for (int j = 0; j < 4; ++j)
        T[(size_t)(bx + y + 8 * j) * DIM + by + x] = __float2half(tile[x][y + 8 * j]);
}

// ---------------- GEMM tile constants: 64x128 tiles, 128 threads, 2-stage ----------------
#define NKT (DIM / 64)
#define A_BYTES (64 * 128)            // 8 KB
#define B_BYTES (128 * 128)           // 16 KB
#define STAGE_B (A_BYTES + B_BYTES)   // 24 KB
#define GEMM_SMEM (2 * STAGE_B)       // 48 KB

// ---------------- fused Q/K/V projection GEMM (one launch, z picks mode) ----------------
__global__ __launch_bounds__(128, 4) void qkv_gemm_kernel(
    const __half* __restrict__ Xh, const __half* __restrict__ Yh,
    const __half* __restrict__ WTq, const __half* __restrict__ WTk, const __half* __restrict__ WTv,
    const float* __restrict__ bq, const float* __restrict__ bk, const float* __restrict__ bv,
    const int* __restrict__ pos_q, const int* __restrict__ pos_kv,
    __half* __restrict__ Qh, __half* __restrict__ Kh, __half* __restrict__ Vh)
{
    extern __shared__ char sm[];
    const uint32_t sbase = smem_u32(sm);
    const int z = blockIdx.z;
    const __half* A = (z == 0) ? Xh : Yh;
    const __half* B = (z == 0) ? WTq : (z == 1) ? WTk : WTv;
    const float* bias = (z == 0) ? bq : (z == 1) ? bk : bv;
    const int* pos = (z == 0) ? pos_q : pos_kv;
    __half* Ch = (z == 0) ? Qh : (z == 1) ? Kh : Vh;

    const int tid  = threadIdx.x;
    const int lane = tid & 31;
    const int wid  = tid >> 5;      // 0..3
    const int warpM = wid & 1;      // 0..1  (32 rows each)
    const int warpN = wid >> 1;     // 0..1  (64 cols each)
    const int m0 = blockIdx.y * 64;
    const int n0 = blockIdx.x * 128;

    float c[2][8][4];
    #pragma unroll
    for (int i = 0; i < 2; ++i)
        #pragma unroll
        for (int j = 0; j < 8; ++j)
            #pragma unroll
            for (int q = 0; q < 4; ++q) c[i][j][q] = 0.f;

    const int rr0 = tid >> 3;       // 0..15
    const int cc  = tid & 7;

    auto issue_stage = [&](int kt, int s) {
        const uint32_t st = sbase + s * STAGE_B;
        // A tile: 64 rows (4 chunks/thread)
        #pragma unroll
        for (int i = 0; i < 4; ++i) {
            int r = rr0 + i * 16;
            uint32_t sw = (uint32_t)(r * 128 + ((cc ^ (r & 7)) << 4));
            const char* ga = (const char*)(A + (size_t)(m0 + r) * DIM + kt * 64 + cc * 8);
            CP_ASYNC16(st + sw, ga);
        }
        // B tile: 128 rows (8 chunks/thread)
        #pragma unroll
        for (int i = 0; i < 8; ++i) {
            int r = rr0 + i * 16;
            uint32_t sw = (uint32_t)(r * 128 + ((cc ^ (r & 7)) << 4));
            const char* gb = (const char*)(B + (size_t)(n0 + r) * DIM + kt * 64 + cc * 8);
            CP_ASYNC16(st + A_BYTES + sw, gb);
        }
        CP_COMMIT();
    };

    const int lrow8 = ((lane >> 3) & 1) * 8 + (lane & 7);
    const int lcol16 = (lane >> 4) * 16;

    issue_stage(0, 0);

    for (int kt = 0; kt < NKT; ++kt) {
        CP_WAIT(0);
        __syncthreads();
        if (kt + 1 < NKT) issue_stage(kt + 1, (kt + 1) & 1);

        const uint32_t ab = sbase + (kt & 1) * STAGE_B;
        const uint32_t bb = ab + A_BYTES;

        #pragma unroll
        for (int ks = 0; ks < 4; ++ks) {
            const int kb = ks * 32;
            uint32_t af[2][4];
            #pragma unroll
            for (int i = 0; i < 2; ++i) {
                int row = warpM * 32 + i * 16 + lrow8;
                int col = kb + lcol16;
                uint32_t ad = ab + row * 128 + ((((col >> 4) ^ (row & 7)) & 7) << 4);
                LDSM_X4(af[i][0], af[i][1], af[i][2], af[i][3], ad);
            }
            uint32_t bf[4][4];
            #pragma unroll
            for (int jj = 0; jj < 4; ++jj) {
                int nrow = warpN * 64 + jj * 16 + lrow8;
                int col = kb + lcol16;
                uint32_t bd = bb + nrow * 128 + ((((col >> 4) ^ (nrow & 7)) & 7) << 4);
                LDSM_X4(bf[jj][0], bf[jj][1], bf[jj][2], bf[jj][3], bd);
            }
            #pragma unroll
            for (int i = 0; i < 2; ++i) {
                #pragma unroll
                for (int j = 0; j < 8; ++j) {
                    const int jj = j >> 1, sel = j & 1;
                    MMA16816(c[i][j], af[i], bf[jj][sel], bf[jj][sel + 2]);
                }
            }
        }
    }

    // ---------------- fused epilogue ----------------
    if (z == 2) {
        #pragma unroll
        for (int i = 0; i < 2; ++i) {
            #pragma unroll
            for (int j = 0; j < 8; ++j) {
                int row = m0 + warpM * 32 + i * 16 + (lane >> 2);
                int col = n0 + warpN * 64 + j * 8 + (lane & 3) * 2;
                float b0v = bias[col], b1v = bias[col + 1];
                *(__half2*)&Ch[(size_t)row * DIM + col] =
                    __floats2half2_rn(c[i][j][0] + b0v, c[i][j][1] + b1v);
                *(__half2*)&Ch[(size_t)(row + 8) * DIM + col] =
                    __floats2half2_rn(c[i][j][2] + b0v, c[i][j][3] + b1v);
            }
        }
    } else {
        const float scale = (z == 0) ? QSCALE : 1.0f;
        #pragma unroll
        for (int i = 0; i < 2; ++i) {
            int rowA = m0 + warpM * 32 + i * 16 + (lane >> 2);
            int rowB = rowA + 8;
            int pA0 = pos[2 * rowA], pA1 = pos[2 * rowA + 1];
            int pB0 = pos[2 * rowB], pB1 = pos[2 * rowB + 1];
            #pragma unroll
            for (int jj = 0; jj < 4; ++jj) {
                const int j = (jj < 2) ? jj : jj + 2;   // 0,1,4,5
                const int half = (j >= 4);
                int col = n0 + warpN * 64 + j * 8 + (lane & 3) * 2;
                int f0 = (j & 1) * 8 + (lane & 3) * 2;
                int pA = half ? pA1 : pA0;
                int pB = half ? pB1 : pB0;
                float cA0 = g_cosT[pA * 16 + f0], cA1 = g_cosT[pA * 16 + f0 + 1];
                float sA0 = g_sinT[pA * 16 + f0], sA1 = g_sinT[pA * 16 + f0 + 1];
                float cB0 = g_cosT[pB * 16 + f0], cB1 = g_cosT[pB * 16 + f0 + 1];
                float sB0 = g_sinT[pB * 16 + f0], sB1 = g_sinT[pB * 16 + f0 + 1];
                float b1x = bias[col], b1y = bias[col + 1];
                float b2x = bias[col + 16], b2y = bias[col + 17];

                {
                    float v1x = c[i][j][0] + b1x,     v1y = c[i][j][1] + b1y;
                    float v2x = c[i][j + 2][0] + b2x, v2y = c[i][j + 2][1] + b2y;
                    *(__half2*)&Ch[(size_t)rowA * DIM + col] =
                        __floats2half2_rn((v1x * cA0 - v2x * sA0) * scale,
                                          (v1y * cA1 - v2y * sA1) * scale);
                    *(__half2*)&Ch[(size_t)rowA * DIM + col + 16] =
                        __floats2half2_rn((v2x * cA0 + v1x * sA0) * scale,
                                          (v2y * cA1 + v1y * sA1) * scale);
                }
                {
                    float v1x = c[i][j][2] + b1x,     v1y = c[i][j][3] + b1y;
                    float v2x = c[i][j + 2][2] + b2x, v2y = c[i][j + 2][3] + b2y;
                    *(__half2*)&Ch[(size_t)rowB * DIM + col] =
                        __floats2half2_rn((v1x * cB0 - v2x * sB0) * scale,
                                          (v1y * cB1 - v2y * sB1) * scale);
                    *(__half2*)&Ch[(size_t)rowB * DIM + col + 16] =
                        __floats2half2_rn((v2x * cB0 + v1x * sB0) * scale,
                                          (v2y * cB1 + v1y * sB1) * scale);
                }
            }
        }
    }
}

// ---------------- final output GEMM: out = Aoh @ WTo^T + bo (fp32) ----------------
__global__ __launch_bounds__(128, 4) void out_gemm_kernel(
    const __half* __restrict__ A, const __half* __restrict__ B,
    const float* __restrict__ bias, float* __restrict__ Cf)
{
    extern __shared__ char sm[];
    const uint32_t sbase = smem_u32(sm);
    const int tid  = threadIdx.x;
    const int lane = tid & 31;
    const int wid  = tid >> 5;
    const int warpM = wid & 1;
    const int warpN = wid >> 1;
    const int m0 = blockIdx.y * 64;
    const int n0 = blockIdx.x * 128;

    float c[2][8][4];
    #pragma unroll
    for (int i = 0; i < 2; ++i)
        #pragma unroll
        for (int j = 0; j < 8; ++j)
            #pragma unroll
            for (int q = 0; q < 4; ++q) c[i][j][q] = 0.f;

    const int rr0 = tid >> 3;
    const int cc  = tid & 7;

    auto issue_stage = [&](int kt, int s) {
        const uint32_t st = sbase + s * STAGE_B;
        #pragma unroll
        for (int i = 0; i < 4; ++i) {
            int r = rr0 + i * 16;
            uint32_t sw = (uint32_t)(r * 128 + ((cc ^ (r & 7)) << 4));
            const char* ga = (const char*)(A + (size_t)(m0 + r) * DIM + kt * 64 + cc * 8);
            CP_ASYNC16(st + sw, ga);
        }
        #pragma unroll
        for (int i = 0; i < 8; ++i) {
            int r = rr0 + i * 16;
            uint32_t sw = (uint32_t)(r * 128 + ((cc ^ (r & 7)) << 4));
            const char* gb = (const char*)(B + (size_t)(n0 + r) * DIM + kt * 64 + cc * 8);
            CP_ASYNC16(st + A_BYTES + sw, gb);
        }
        CP_COMMIT();
    };

    const int lrow8 = ((lane >> 3) & 1) * 8 + (lane & 7);
    const int lcol16 = (lane >> 4) * 16;

    issue_stage(0, 0);

    for (int kt = 0; kt < NKT; ++kt) {
        CP_WAIT(0);
        __syncthreads();
        if (kt + 1 < NKT) issue_stage(kt + 1, (kt + 1) & 1);

        const uint32_t ab = sbase + (kt & 1) * STAGE_B;
        const uint32_t bb = ab + A_BYTES;

        #pragma unroll
        for (int ks = 0; ks < 4; ++ks) {
            const int kb = ks * 32;
            uint32_t af[2][4];
            #pragma unroll
            for (int i = 0; i < 2; ++i) {
                int row = warpM * 32 + i * 16 + lrow8;
                int col = kb + lcol16;
                uint32_t ad = ab + row * 128 + ((((col >> 4) ^ (row & 7)) & 7) << 4);
                LDSM_X4(af[i][0], af[i][1], af[i][2], af[i][3], ad);
            }
            uint32_t bf[4][4];
            #pragma unroll
            for (int jj = 0; jj < 4; ++jj) {
                int nrow = warpN * 64 + jj * 16 + lrow8;
                int col = kb + lcol16;
                uint32_t bd = bb + nrow * 128 + ((((col >> 4) ^ (nrow & 7)) & 7) << 4);
                LDSM_X4(bf[jj][0], bf[jj][1], bf[jj][2], bf[jj][3], bd);
            }
            #pragma unroll
            for (int i = 0; i < 2; ++i) {
                #pragma unroll
                for (int j = 0; j < 8; ++j) {
                    const int jj = j >> 1, sel = j & 1;
                    MMA16816(c[i][j], af[i], bf[jj][sel], bf[jj][sel + 2]);
                }
            }
        }
    }

    #pragma unroll
    for (int i = 0; i < 2; ++i) {
        #pragma unroll
        for (int j = 0; j < 8; ++j) {
            int row = m0 + warpM * 32 + i * 16 + (lane >> 2);
            int col = n0 + warpN * 64 + j * 8 + (lane & 3) * 2;
            float b0v = bias[col], b1v = bias[col + 1];
            float2 o0 = {c[i][j][0] + b0v, c[i][j][1] + b1v};
            float2 o1 = {c[i][j][2] + b0v, c[i][j][3] + b1v};
            *(float2*)&Cf[(size_t)row * DIM + col] = o0;
            *(float2*)&Cf[(size_t)(row + 8) * DIM + col] = o1;
        }
    }
}

// ---------------- fp16 flash attention: 64q x 64kv CTAs (4 warps), 3-stage pipeline ----------------
#define FS_STAGE 16384
#define FS_NSTG 3
#define FS_Q_OFF (FS_NSTG * FS_STAGE)           // 49152
#define FS_SMEM (FS_Q_OFF + 8192)               // 57344
#define FS_NT (SEQ / 64)                        // 16

__global__ __launch_bounds__(128, 4) void flash16_kernel(
    const __half* __restrict__ Qh, const __half* __restrict__ Kh,
    const __half* __restrict__ Vh, __half* __restrict__ Ao)
{
    extern __shared__ char sm[];
    const uint32_t sb = smem_u32(sm);
    const int tid  = threadIdx.x;
    const int lane = tid & 31;
    const int wid  = tid >> 5;       // 0..3
    const int qb   = blockIdx.x * 64;
    const int h    = blockIdx.y;
    const int b    = blockIdx.z;
    const size_t qrow0 = (size_t)b * SEQ + qb;
    const int colh = h * DH;

    const int lrow8  = ((lane >> 3) & 1) * 8 + (lane & 7);
    const int lcol16 = (lane >> 4) * 16;

    #pragma unroll
    for (int i = 0; i < 4; ++i) {
        int idx = tid + i * 128;
        int r = idx >> 3, c = idx & 7;
        uint32_t sw = (uint32_t)(r * 128 + ((c ^ (r & 7)) << 4));
        size_t goff = (qrow0 + r) * DIM + colh + c * 8;
        CP_ASYNC16(sb + FS_Q_OFF + sw, (const char*)(Qh + goff));
    }
    CP_COMMIT();

    auto issue_kv = [&](int kt, int s) {
        const size_t rowbase = (size_t)b * SEQ + (size_t)kt * 64;
        const uint32_t st = sb + s * FS_STAGE;
        #pragma unroll
        for (int i = 0; i < 4; ++i) {
            int idx = tid + i * 128;
            int r = idx >> 3, c = idx & 7;
            uint32_t sw = (uint32_t)(r * 128 + ((c ^ (r & 7)) << 4));
            size_t goff = (rowbase + r) * DIM + colh + c * 8;
            CP_ASYNC16(st + sw,        (const char*)(Kh + goff));
            CP_ASYNC16(st + 8192 + sw, (const char*)(Vh + goff));
        }
        CP_COMMIT();
    };

    issue_kv(0, 0);
    issue_kv(1, 1);
    CP_WAIT(1);
    __syncthreads();

    uint32_t qhf[4][4];
    #pragma unroll
    for (int kc = 0; kc < 4; ++kc) {
        int row = wid * 16 + lrow8;
        int col = kc * 32 + lcol16;
        uint32_t ad = sb + FS_Q_OFF + row * 128 + ((((col >> 4) ^ (row & 7)) & 7) << 4);
        LDSM_X4(qhf[kc][0], qhf[kc][1], qhf[kc][2], qhf[kc][3], ad);
    }

    float o[8][4];
    #pragma unroll
    for (int i = 0; i < 8; ++i)
        #pragma unroll
        for (int q = 0; q < 4; ++q) o[i][q] = 0.f;
    float m0 = -1e30f, m1 = -1e30f, l0 = 0.f, l1 = 0.f;

    int stg = 0;
    for (int kt = 0; kt < FS_NT; ++kt) {
        if (kt) {
            if (kt >= FS_NT - 2) CP_WAIT(0);
            else                 CP_WAIT(1);
            __syncthreads();
        }
        if (kt + 2 < FS_NT) {
            int s2 = stg + 2;
            if (s2 >= FS_NSTG) s2 -= FS_NSTG;
            issue_kv(kt + 2, s2);
        }

        const uint32_t kb = sb + stg * FS_STAGE;
        const uint32_t vb = kb + 8192;
        if (++stg == FS_NSTG) stg = 0;

        float s[8][4];
        #pragma unroll
        for (int i = 0; i < 8; ++i)
            #pragma unroll
            for (int q = 0; q < 4; ++q) s[i][q] = 0.f;

        #pragma unroll
        for (int kc = 0; kc < 4; ++kc) {
            const int col = kc * 32 + lcol16;
            #pragma unroll
            for (int nb2 = 0; nb2 < 4; ++nb2) {
                int row = nb2 * 16 + lrow8;
                uint32_t ad = kb + row * 128 + ((((col >> 4) ^ (row & 7)) & 7) << 4);
                uint32_t f0, f1, f2, f3;
                LDSM_X4(f0, f1, f2, f3, ad);
                MMA16816(s[2 * nb2],     qhf[kc], f0, f2);
                MMA16816(s[2 * nb2 + 1], qhf[kc], f1, f3);
            }
        }

        float mx0 = -1e30f, mx1 = -1e30f;
        #pragma unroll
        for (int nb = 0; nb < 8; ++nb) {
            mx0 = fmaxf(mx0, fmaxf(s[nb][0], s[nb][1]));
            mx1 = fmaxf(mx1, fmaxf(s[nb][2], s[nb][3]));
        }
        mx0 = fmaxf(mx0, __shfl_xor_sync(0xffffffffu, mx0, 1));
        mx0 = fmaxf(mx0, __shfl_xor_sync(0xffffffffu, mx0, 2));
        mx1 = fmaxf(mx1, __shfl_xor_sync(0xffffffffu, mx1, 1));
        mx1 = fmaxf(mx1, __shfl_xor_sync(0xffffffffu, mx1, 2));
        float mn0 = fmaxf(m0, mx0), mn1 = fmaxf(m1, mx1);
        float cr0 = ex2f(m0 - mn0), cr1 = ex2f(m1 - mn1);
        m0 = mn0; m1 = mn1;

        float ls0 = 0.f, ls1 = 0.f;
        uint32_t a[4][4];
        #pragma unroll
        for (int nb = 0; nb < 8; ++nb) {
            float p0 = ex2f(s[nb][0] - mn0);
            float p1 = ex2f(s[nb][1] - mn0);
            float p2 = ex2f(s[nb][2] - mn1);
            float p3 = ex2f(s[nb][3] - mn1);
            ls0 += p0 + p1;
            ls1 += p2 + p3;
            __half2 h01 = __floats2half2_rn(p0, p1);
            __half2 h23 = __floats2half2_rn(p2, p3);
            int kc = nb >> 1;
            if ((nb & 1) == 0) {
                a[kc][0] = *(uint32_t*)&h01;
                a[kc][1] = *(uint32_t*)&h23;
            } else {
                a[kc][2] = *(uint32_t*)&h01;
                a[kc][3] = *(uint32_t*)&h23;
            }
        }
        l0 = l0 * cr0 + ls0;
        l1 = l1 * cr1 + ls1;
        #pragma unroll
        for (int db = 0; db < 8; ++db) {
            o[db][0] *= cr0; o[db][1] *= cr0;
            o[db][2] *= cr1; o[db][3] *= cr1;
        }

        #pragma unroll
        for (int kc = 0; kc < 4; ++kc) {
            int row = kc * 16 + lrow8;
            #pragma unroll
            for (int db2 = 0; db2 < 4; ++db2) {
                int col = db2 * 32 + lcol16;
                uint32_t ad = vb + row * 128 + ((((col >> 4) ^ (row & 7)) & 7) << 4);
                uint32_t f0, f1, f2, f3;
                LDSM_X4_T(f0, f1, f2, f3, ad);
                MMA16816(o[2 * db2],     a[kc], f0, f1);
                MMA16816(o[2 * db2 + 1], a[kc], f2, f3);
            }
        }
    }

    l0 += __shfl_xor_sync(0xffffffffu, l0, 1);
    l0 += __shfl_xor_sync(0xffffffffu, l0, 2);
    l1 += __shfl_xor_sync(0xffffffffu, l1, 1);
    l1 += __shfl_xor_sync(0xffffffffu, l1, 2);

    float inv0 = 1.0f / l0, inv1 = 1.0f / l1;
    size_t r0 = qrow0 + wid * 16 + (lane >> 2);
    size_t r1 = r0 + 8;
    int cb = colh + (lane & 3) * 2;
    #pragma unroll
    for (int db = 0; db < 8; ++db) {
        __half2 w0 = __floats2half2_rn(o[db][0] * inv0, o[db][1] * inv0);
        __half2 w1 = __floats2half2_rn(o[db][2] * inv1, o[db][3] * inv1);
        *(__half2*)&Ao[r0 * DIM + cb + db * 8] = w0;
        *(__half2*)&Ao[r1 * DIM + cb + db * 8] = w1;
    }
}

// ---------------- launch ----------------
extern "C" void kernel_launch(void* const* d_in, const int* in_sizes, int n_in,
                              void* d_out, int out_size) {
    const float* x      = (const float*)d_in[0];
    const float* y      = (const float*)d_in[1];
    const int*   pos_q  = (const int*)d_in[2];
    const int*   pos_kv = (const int*)d_in[3];
    const float* Wq = (const float*)d_in[4];
    const float* bq = (const float*)d_in[5];
    const float* Wk = (const float*)d_in[6];
    const float* bk = (const float*)d_in[7];
    const float* Wv = (const float*)d_in[8];
    const float* bv = (const float*)d_in[9];
    const float* Wo = (const float*)d_in[10];
    const float* bo = (const float*)d_in[11];
    float* out = (float*)d_out;

    __half *Xh, *Yh, *WTq, *WTk, *WTv, *WTo;
    __half *Qhp, *Khp, *Vhp, *Aohp;
    cudaGetSymbolAddress((void**)&Xh, g_Xh);
    cudaGetSymbolAddress((void**)&Yh, g_Yh);
    cudaGetSymbolAddress((void**)&WTq, g_WTq);
    cudaGetSymbolAddress((void**)&WTk, g_WTk);
    cudaGetSymbolAddress((void**)&WTv, g_WTv);
    cudaGetSymbolAddress((void**)&WTo, g_WTo);
    cudaGetSymbolAddress((void**)&Qhp, g_Qh);
    cudaGetSymbolAddress((void**)&Khp, g_Kh);
    cudaGetSymbolAddress((void**)&Vhp, g_Vh);
    cudaGetSymbolAddress((void**)&Aohp, g_Aoh);

    cudaFuncSetAttribute(qkv_gemm_kernel, cudaFuncAttributeMaxDynamicSharedMemorySize, GEMM_SMEM);
    cudaFuncSetAttribute(out_gemm_kernel, cudaFuncAttributeMaxDynamicSharedMemorySize, GEMM_SMEM);
    cudaFuncSetAttribute(flash16_kernel, cudaFuncAttributeMaxDynamicSharedMemorySize, FS_SMEM);

    const int n4 = (ROWS * DIM) / 4;
    f2h2_kernel<<<dim3((n4 + 255) / 256, 2), 256>>>(x, y, Xh, Yh, n4);

    transpose4_kernel<<<dim3(DIM / 32, DIM / 32, 4), dim3(32, 8)>>>(
        Wq, Wk, Wv, Wo, WTq, WTk, WTv, WTo);

    qkv_gemm_kernel<<<dim3(DIM / 128, ROWS / 64, 3), 128, GEMM_SMEM>>>(
        Xh, Yh, WTq, WTk, WTv, bq, bk, bv, pos_q, pos_kv,
        Qhp, Khp, Vhp);

    flash16_kernel<<<dim3(SEQ / 64, HEADS, BATCH), 128, FS_SMEM>>>(
        Qhp, Khp, Vhp, Aohp);

    out_gemm_kernel<<<dim3(DIM / 128, ROWS / 64), 128, GEMM_SMEM>>>(Aohp, WTo, bo, out);
}